// round 15
// baseline (speedup 1.0000x reference)
#include <cuda_runtime.h>
#include <cuda_bf16.h>
#include <cstdint>

#define EPS 1e-9f
#define BATCH 128
#define NN 400
#define HH 128
#define NSQ (NN * NN)          // 160000
#define NQ4 (NSQ / 4)          // 40000
#define S_HN (HH * NN)         // 51200
#define S_HH (HH * HH)         // 16384
#define KTOP 32000

typedef __nv_bfloat16 bf16;
typedef unsigned long long ull;

// ---------------- scratch -----------------------------------------------------
__device__ float g_xf[BATCH * NSQ];                        // x2 fp32 (written by sym)
__device__ float g_delta[BATCH * NSQ];
__device__ float g_degp[BATCH * 4 * NN];
__device__ float g_part[7 * BATCH * HH];
__device__ bf16 g_ah[BATCH * NSQ], g_al[BATCH * NSQ];
__device__ bf16 g_anh[BATCH * NSQ], g_anl[BATCH * NSQ];
__device__ bf16 g_o1h[BATCH * S_HN], g_o1l[BATCH * S_HN];
__device__ bf16 g_o2ah[BATCH * S_HH], g_o2al[BATCH * S_HH];
__device__ bf16 g_o2th[BATCH * S_HN], g_o2tl[BATCH * S_HN];
__device__ bf16 g_y1h[BATCH * S_HN], g_y1l[BATCH * S_HN];
__device__ bf16 g_wh[272384], g_wl[272384];
__device__ ull g_thresh[BATCH];
__device__ float g_rs[BATCH * NN];

#define W_E1 0
#define W_E2 51200
#define W_D2 102400
#define W_D1 153600
#define W_G1 204800
#define W_G2T 256000

__device__ __forceinline__ void fsplit(float v, bf16* h, bf16* l) {
    bf16 hh = __float2bfloat16(v);
    *h = hh;
    *l = __float2bfloat16(v - __bfloat162float(hh));
}
__device__ __forceinline__ void fsplit4(const float* v, uint2* ph, uint2* pl) {
    unsigned short h[4], l[4];
    #pragma unroll
    for (int e = 0; e < 4; e++) {
        bf16 hh = __float2bfloat16(v[e]);
        h[e] = __bfloat16_as_ushort(hh);
        l[e] = __bfloat16_as_ushort(__float2bfloat16(v[e] - __bfloat162float(hh)));
    }
    ph->x = (unsigned)h[0] | ((unsigned)h[1] << 16);
    ph->y = (unsigned)h[2] | ((unsigned)h[3] << 16);
    pl->x = (unsigned)l[0] | ((unsigned)l[1] << 16);
    pl->y = (unsigned)l[2] | ((unsigned)l[3] << 16);
}
__device__ __forceinline__ void unsplit4(uint2 ph, uint2 pl, float* v) {
    v[0] = __uint_as_float(ph.x << 16) + __uint_as_float(pl.x << 16);
    v[1] = __uint_as_float(ph.x & 0xffff0000u) + __uint_as_float(pl.x & 0xffff0000u);
    v[2] = __uint_as_float(ph.y << 16) + __uint_as_float(pl.y << 16);
    v[3] = __uint_as_float(ph.y & 0xffff0000u) + __uint_as_float(pl.y & 0xffff0000u);
}

// ---------------- combined weight prep (one launch) ------------------------------
__global__ void wsplit_all_k(const float* __restrict__ e1, const float* __restrict__ e2,
                             const float* __restrict__ d2, const float* __restrict__ d1,
                             const float* __restrict__ g1, const float* __restrict__ g2,
                             bf16* __restrict__ wh, bf16* __restrict__ wl) {
    int i = blockIdx.x * 256 + threadIdx.x;   // 0..51199
    int w = blockIdx.y;                       // 0..5
    if (w < 5) {
        const float* src = (w == 0) ? e1 : (w == 1) ? e2 : (w == 2) ? d2
                         : (w == 3) ? d1 : g1;
        int off = w * 51200;
        fsplit(src[i], &wh[off + i], &wl[off + i]);
    } else if (i < S_HH) {
        int g = i >> 7, f = i & 127;
        fsplit(g2[f * HH + g], &wh[W_G2T + i], &wl[W_G2T + i]);
    }
}

// ---------------- fisher -> bf16 split (MUFU __logf, R13-proven) -----------------
__global__ void fisher_k(const float* __restrict__ x,
                         bf16* __restrict__ xh, bf16* __restrict__ xl) {
    int t = blockIdx.x * 256 + threadIdx.x;
    int b = blockIdx.y;
    if (t >= NQ4) return;
    size_t base = (size_t)b * NSQ;
    float x00 = x[base];
    float d = 0.5f * __logf((1.f + x00 + EPS) / (1.f - x00 + EPS));
    float rd = 1.f / d;
    float4 v = ((const float4*)(x + base))[t];
    float o[4];
    o[0] = 0.5f * __logf((1.f + v.x + EPS) / (1.f - v.x + EPS)) * rd;
    o[1] = 0.5f * __logf((1.f + v.y + EPS) / (1.f - v.y + EPS)) * rd;
    o[2] = 0.5f * __logf((1.f + v.z + EPS) / (1.f - v.z + EPS)) * rd;
    o[3] = 0.5f * __logf((1.f + v.w + EPS) / (1.f - v.w + EPS)) * rd;
    uint2 ph, pl;
    fsplit4(o, &ph, &pl);
    ((uint2*)(xh + base))[t] = ph;
    ((uint2*)(xl + base))[t] = pl;
}

// ---------------- symmetric-pair symmetrize: x2 fp32 + split ---------------------
__global__ void sym2_k(float* __restrict__ x2, const float* __restrict__ delta,
                       bf16* __restrict__ xh, bf16* __restrict__ xl) {
    int b = blockIdx.y;
    int p = blockIdx.x;
    int ti = 0, rem = p;
    while (rem >= 13 - ti) { rem -= 13 - ti; ti++; }
    int tj = ti + rem;
    int i0 = ti * 32, j0 = tj * 32;
    int tx = threadIdx.x, ty = threadIdx.y;
    __shared__ float shA[32][33];
    __shared__ float shB[32][33];
    size_t base = (size_t)b * NSQ;
    bool diag = (ti == tj);

    {
        int r = i0 + ty, c = j0 + tx * 4;
        float4 v = make_float4(0.f, 0.f, 0.f, 0.f);
        if (r < NN && c < NN) v = *(const float4*)&delta[base + (size_t)r * NN + c];
        shA[ty][tx * 4 + 0] = v.x; shA[ty][tx * 4 + 1] = v.y;
        shA[ty][tx * 4 + 2] = v.z; shA[ty][tx * 4 + 3] = v.w;
    }
    if (!diag) {
        int r = j0 + ty, c = i0 + tx * 4;
        float4 v = make_float4(0.f, 0.f, 0.f, 0.f);
        if (r < NN && c < NN) v = *(const float4*)&delta[base + (size_t)r * NN + c];
        shB[ty][tx * 4 + 0] = v.x; shB[ty][tx * 4 + 1] = v.y;
        shB[ty][tx * 4 + 2] = v.z; shB[ty][tx * 4 + 3] = v.w;
    }
    __syncthreads();

    {
        int r = i0 + ty, c0 = j0 + tx * 4;
        if (r < NN && c0 < NN) {
            size_t idx = base + (size_t)r * NN + c0;
            float o[4];
            unsplit4(*(const uint2*)&xh[idx], *(const uint2*)&xl[idx], o);
            #pragma unroll
            for (int e = 0; e < 4; e++) {
                int c = c0 + e;
                float dT = diag ? shA[tx * 4 + e][ty] : shB[tx * 4 + e][ty];
                if (r != c) o[e] += 0.5f * (shA[ty][tx * 4 + e] + dT);
            }
            *(float4*)&x2[idx] = make_float4(o[0], o[1], o[2], o[3]);
            uint2 ph, pl;
            fsplit4(o, &ph, &pl);
            *(uint2*)&xh[idx] = ph;
            *(uint2*)&xl[idx] = pl;
        }
    }
    if (!diag) {
        int r = j0 + ty, c0 = i0 + tx * 4;
        if (r < NN && c0 < NN) {
            size_t idx = base + (size_t)r * NN + c0;
            float o[4];
            unsplit4(*(const uint2*)&xh[idx], *(const uint2*)&xl[idx], o);
            #pragma unroll
            for (int e = 0; e < 4; e++) {
                int c = c0 + e;
                if (r != c) o[e] += 0.5f * (shB[ty][tx * 4 + e] + shA[tx * 4 + e][ty]);
            }
            *(float4*)&x2[idx] = make_float4(o[0], o[1], o[2], o[3]);
            uint2 ph, pl;
            fsplit4(o, &ph, &pl);
            *(uint2*)&xh[idx] = ph;
            *(uint2*)&xl[idx] = pl;
        }
    }
}

// ---------------- keys ------------------------------------------------------------
__device__ __forceinline__ unsigned make_vkey(float v) {
    unsigned u = __float_as_uint(v);
    return (u & 0x80000000u) ? ~u : (u | 0x80000000u);
}
__device__ __forceinline__ ull make_key(float v, unsigned t) {
    return ((ull)make_vkey(v) << 32) | (ull)(~t);
}

// ---------------- exact top-k: two 12-bit passes, 1024 threads --------------------
#define RNT 1024
__global__ void radix_select_k(const float* __restrict__ x2,
                               ull* __restrict__ thresh) {
    const int b = blockIdx.x;
    const float4* xp4 = (const float4*)(x2 + (size_t)b * NSQ);
    extern __shared__ unsigned rsm[];
    unsigned* hist = rsm;                 // [2][4096]
    ull* buf = (ull*)(rsm + 8192);        // [2048]
    __shared__ unsigned wsum[32];
    __shared__ unsigned s_bin, s_rem, s_cnt;
    int tid = threadIdx.x;
    int lane = tid & 31, wid = tid >> 5;
    int hsel = (wid & 1) * 4096;
    if (tid == 0) { s_rem = KTOP; s_cnt = 0; }

    unsigned b1 = 0;
    #pragma unroll
    for (int pass = 0; pass < 2; pass++) {
        for (int i = tid; i < 8192; i += RNT) hist[i] = 0;
        __syncthreads();
        for (int t = tid; t < 40960; t += RNT) {
            bool inr = t < NQ4;
            float4 v = inr ? xp4[t] : make_float4(0.f, 0.f, 0.f, 0.f);
            float vv[4] = {v.x, v.y, v.z, v.w};
            #pragma unroll
            for (int e = 0; e < 4; e++) {
                unsigned vk = make_vkey(vv[e]);
                bool ok = inr && (pass == 0 || (vk >> 20) == b1);
                unsigned bin = (pass == 0) ? (vk >> 20) : ((vk >> 8) & 4095);
                unsigned active = __ballot_sync(0xffffffffu, ok);
                if (ok) {
                    unsigned peers = __match_any_sync(active, bin);
                    int leader = __ffs(peers) - 1;
                    if (lane == leader) atomicAdd(&hist[hsel + bin], __popc(peers));
                }
            }
        }
        __syncthreads();
        unsigned cs = 0;
        #pragma unroll
        for (int k = 0; k < 4; k++) {
            int bin = 4095 - 4 * tid - k;
            cs += hist[bin] + hist[4096 + bin];
        }
        unsigned v = cs;
        #pragma unroll
        for (int o = 1; o < 32; o <<= 1) {
            unsigned u = __shfl_up_sync(0xffffffffu, v, o);
            if (lane >= o) v += u;
        }
        if (lane == 31) wsum[wid] = v;
        __syncthreads();
        if (wid == 0) {
            unsigned w = wsum[lane];
            #pragma unroll
            for (int o = 1; o < 32; o <<= 1) {
                unsigned u = __shfl_up_sync(0xffffffffu, w, o);
                if (lane >= o) w += u;
            }
            wsum[lane] = w;
        }
        __syncthreads();
        unsigned incl = v + (wid ? wsum[wid - 1] : 0);
        unsigned excl = incl - cs;
        unsigned rem = s_rem;
        if (rem > excl && rem <= incl) {
            unsigned c = excl;
            #pragma unroll
            for (int k = 0; k < 4; k++) {
                int bin = 4095 - 4 * tid - k;
                unsigned bc = hist[bin] + hist[4096 + bin];
                if (rem <= c + bc) { s_bin = (unsigned)bin; s_rem = rem - c; break; }
                c += bc;
            }
        }
        __syncthreads();
        if (pass == 0) b1 = s_bin;
    }
    unsigned pref24 = (b1 << 12) | s_bin;
    unsigned remf = s_rem;

    for (int t = tid; t < NQ4; t += RNT) {
        float4 v = xp4[t];
        float vv[4] = {v.x, v.y, v.z, v.w};
        #pragma unroll
        for (int e = 0; e < 4; e++) {
            if ((make_vkey(vv[e]) >> 8) == pref24) {
                unsigned p = atomicAdd(&s_cnt, 1);
                if (p < 2048) buf[p] = make_key(vv[e], (unsigned)(t * 4 + e));
            }
        }
    }
    __syncthreads();
    unsigned n = min(s_cnt, 2048u);
    for (int t = tid; t < (int)n; t += RNT) {
        ull k = buf[t];
        unsigned c = 0;
        for (unsigned j = 0; j < n; j++) c += (buf[j] > k);
        if (c == remf - 1) thresh[b] = k;
    }
}

// ---------------- fused mask + partial column degrees (float4) -------------------
__global__ void degp_k(const float* __restrict__ x2, const ull* __restrict__ th,
                       float* __restrict__ part) {
    int q = blockIdx.x, b = blockIdx.y;
    int t = threadIdx.x;   // 128, first 100 active
    if (t >= 100) return;
    ull thr = th[b];
    const float* xb = x2 + (size_t)b * NSQ;
    int j0 = 4 * t;
    float acc[4] = {0.f, 0.f, 0.f, 0.f};
    int i0 = q * 100;
    for (int i = i0; i < i0 + 100; i++) {
        float4 v = *(const float4*)&xb[(size_t)i * NN + j0];
        float vv[4] = {v.x, v.y, v.z, v.w};
        #pragma unroll
        for (int e = 0; e < 4; e++) {
            unsigned r = (unsigned)(i * NN + j0 + e);
            float a = (make_key(vv[e], r) >= thr) ? vv[e] : 0.f;
            if (i == j0 + e && a == 0.f) a = 1.f;
            acc[e] += a;
        }
    }
    size_t base = ((size_t)b * 4 + q) * NN + j0;
    *(float4*)&part[base] = make_float4(acc[0], acc[1], acc[2], acc[3]);
}

// ------- warp-per-row: dinv (from partials) + mask + An split + row means --------
__global__ void __launch_bounds__(256)
an_k(const float* __restrict__ x2, const ull* __restrict__ th,
     const float* __restrict__ part,
     bf16* __restrict__ anh, bf16* __restrict__ anl,
     float* __restrict__ rs) {
    int b = blockIdx.y;
    int tid = threadIdx.x;
    __shared__ float sdv[NN];
    {
        size_t base = (size_t)b * 4 * NN;
        for (int j = tid; j < NN; j += 256) {
            float s = part[base + j] + part[base + NN + j]
                    + part[base + 2 * NN + j] + part[base + 3 * NN + j];
            float dv = rsqrtf(s);
            if (isinf(dv)) dv = 0.f;
            sdv[j] = dv;
        }
    }
    __syncthreads();
    int warp = tid >> 5, lane = tid & 31;
    int i = blockIdx.x * 8 + warp;
    ull thr = th[b];
    size_t roff = (size_t)b * NSQ + (size_t)i * NN;
    float di = sdv[i];
    float acc = 0.f;
    for (int c = lane; c < 100; c += 32) {
        int j0 = c * 4;
        float4 v = *(const float4*)&x2[roff + j0];
        float vv[4] = {v.x, v.y, v.z, v.w};
        float w[4];
        #pragma unroll
        for (int e = 0; e < 4; e++) {
            unsigned r = (unsigned)(i * NN + j0 + e);
            float a = (make_key(vv[e], r) >= thr) ? vv[e] : 0.f;
            if (i == j0 + e && a == 0.f) a = 1.f;
            w[e] = a * di * sdv[j0 + e];
            acc += w[e];
        }
        uint2 ph, pl;
        fsplit4(w, &ph, &pl);
        *(uint2*)&anh[roff + j0] = ph;
        *(uint2*)&anl[roff + j0] = pl;
    }
    #pragma unroll
    for (int o = 16; o > 0; o >>= 1) acc += __shfl_xor_sync(0xffffffffu, acc, o);
    if (lane == 0) rs[b * NN + i] = acc * (1.f / NN);
}

// =============== 2-stage cp.async bf16 split GEMM ================================
#define BM 128
#define BN 64
#define BK 32
#define BKP 40
#define BNP 72
#define ABUF (BM * BKP * 2)
#define ASTG (2 * ABUF)
#define BBUF (BK * BNP * 2)
#define BSTG (2 * BBUF)
#define SMEM_TOT (2 * (ASTG + BSTG))   // 59392 -> 3 CTAs/SM

__device__ __forceinline__ void ldm_x4(uint32_t* r, uint32_t a) {
    asm volatile("ldmatrix.sync.aligned.m8n8.x4.shared.b16 {%0,%1,%2,%3}, [%4];"
        : "=r"(r[0]), "=r"(r[1]), "=r"(r[2]), "=r"(r[3]) : "r"(a));
}
__device__ __forceinline__ void ldm_x2t(uint32_t* r, uint32_t a) {
    asm volatile("ldmatrix.sync.aligned.m8n8.x2.trans.shared.b16 {%0,%1}, [%2];"
        : "=r"(r[0]), "=r"(r[1]) : "r"(a));
}
__device__ __forceinline__ void mma16816(float* d, const uint32_t* a, const uint32_t* b) {
    asm volatile("mma.sync.aligned.m16n8k16.row.col.f32.bf16.bf16.f32 "
        "{%0,%1,%2,%3}, {%4,%5,%6,%7}, {%8,%9}, {%0,%1,%2,%3};"
        : "+f"(d[0]), "+f"(d[1]), "+f"(d[2]), "+f"(d[3])
        : "r"(a[0]), "r"(a[1]), "r"(a[2]), "r"(a[3]), "r"(b[0]), "r"(b[1]));
}
__device__ __forceinline__ void cpa16(uint32_t dst, const bf16* src, bool p) {
    int sz = p ? 16 : 0;
    asm volatile("cp.async.cg.shared.global [%0], [%1], 16, %2;"
        :: "r"(dst), "l"(src), "r"(sz));
}
__device__ __forceinline__ void cp_commit() {
    asm volatile("cp.async.commit_group;");
}
template<int W> __device__ __forceinline__ void cp_wait() {
    asm volatile("cp.async.wait_group %0;" :: "n"(W));
}

// EPI: 0 none, 1 relu+bias[n], 2 relu+bias[n]+skip(bf16 pair), 3 relu+bias[m]
// OUTF bit0: fp32 C; bit1: split bf16 C. FLAT: batch folded into M.
template<int EPI, int TRANSOUT, int OUTF, int FLAT>
__global__ void __launch_bounds__(256)
bgemm_k(const bf16* __restrict__ Ah, const bf16* __restrict__ Al, size_t sA, int lda,
        const bf16* __restrict__ Bh, const bf16* __restrict__ Bl, size_t sB, int ldb,
        const float* __restrict__ bias,
        const bf16* __restrict__ skH, const bf16* __restrict__ skL, int lds,
        float* __restrict__ Cf, bf16* __restrict__ Ch, bf16* __restrict__ Cl,
        size_t sC, int ldc, int M, int N, int K, int MROWS) {
    int bz = FLAT ? 0 : blockIdx.z;
    if (!FLAT) {
        Ah += (size_t)bz * sA; Al += (size_t)bz * sA;
        Bh += (size_t)bz * sB; Bl += (size_t)bz * sB;
    }

    int n0 = blockIdx.x * BN;
    int m0 = blockIdx.y * BM;

    extern __shared__ bf16 dsm[];
    uint32_t smA = (uint32_t)__cvta_generic_to_shared(dsm);
    uint32_t smB = smA + 2 * ASTG;

    int tid = threadIdx.x;
    int warp = tid >> 5, lane = tid & 31;
    int wm = (warp >> 1) * 32;
    int wn = (warp & 1) * 32;
    int gid = lane >> 2, tig = lane & 3;

    const bf16* aSrc[4]; uint32_t aDst[4]; bool aPm[4]; int aC[4];
    #pragma unroll
    for (int it = 0; it < 4; it++) {
        int idx = tid + it * 256;
        int buf = idx >> 9;
        int rem = idx & 511;
        int r = rem >> 2, c = (rem & 3) * 8;
        int m = m0 + r;
        aPm[it] = m < M;
        aC[it] = c;
        aSrc[it] = (buf ? Al : Ah) + (size_t)(aPm[it] ? m : (M - 1)) * lda + c;
        aDst[it] = smA + buf * ABUF + (r * BKP + c) * 2;
    }
    const bf16* bSrc[2]; uint32_t bDst[2]; bool bPn[2]; int bR[2];
    #pragma unroll
    for (int it = 0; it < 2; it++) {
        int idx = tid + it * 256;
        int buf = idx >> 8;
        int rem = idx & 255;
        int r = rem >> 3, c = (rem & 7) * 8;
        bR[it] = r;
        bPn[it] = (n0 + c) < N;
        bSrc[it] = (buf ? Bl : Bh) + (size_t)r * ldb + (n0 + (bPn[it] ? c : 0));
        bDst[it] = smB + buf * BBUF + (r * BNP + c) * 2;
    }

    auto issue = [&](int k0, int stg) {
        #pragma unroll
        for (int it = 0; it < 4; it++)
            cpa16(aDst[it] + stg * ASTG, aSrc[it] + k0, aPm[it] && (k0 + aC[it] < K));
        #pragma unroll
        for (int it = 0; it < 2; it++)
            cpa16(bDst[it] + stg * BSTG, bSrc[it] + (size_t)k0 * ldb,
                  bPn[it] && (k0 + bR[it] < K));
        cp_commit();
    };

    float acc[2][4][4] = {};

    uint32_t aB0 = smA + ((wm + (lane & 15)) * BKP + (lane >> 4) * 8) * 2;
    uint32_t bB0 = smB + ((lane & 15) * BNP + wn) * 2;

    int nk = (K + BK - 1) / BK;
    issue(0, 0);
    for (int t = 0; t < nk; t++) {
        if (t + 1 < nk) { issue((t + 1) * BK, (t + 1) & 1); cp_wait<1>(); }
        else cp_wait<0>();
        __syncthreads();
        int stg = t & 1;
        uint32_t aH = aB0 + stg * ASTG;
        uint32_t aL = aH + ABUF;
        uint32_t bH = bB0 + stg * BSTG;
        uint32_t bL = bH + BBUF;
        #pragma unroll
        for (int kc = 0; kc < 2; kc++) {
            uint32_t ah[2][4], al[2][4];
            ldm_x4(ah[0], aH + kc * 32);
            ldm_x4(ah[1], aH + 16 * BKP * 2 + kc * 32);
            ldm_x4(al[0], aL + kc * 32);
            ldm_x4(al[1], aL + 16 * BKP * 2 + kc * 32);
            #pragma unroll
            for (int ni = 0; ni < 4; ni++) {
                uint32_t bh[2], bl[2];
                ldm_x2t(bh, bH + kc * 16 * BNP * 2 + ni * 16);
                ldm_x2t(bl, bL + kc * 16 * BNP * 2 + ni * 16);
                #pragma unroll
                for (int mi = 0; mi < 2; mi++) {
                    mma16816(acc[mi][ni], ah[mi], bh);
                    mma16816(acc[mi][ni], al[mi], bh);
                    mma16816(acc[mi][ni], ah[mi], bl);
                }
            }
        }
        __syncthreads();
    }

    #pragma unroll
    for (int mi = 0; mi < 2; mi++) {
        #pragma unroll
        for (int ni = 0; ni < 4; ni++) {
            int cbase = n0 + wn + ni * 8 + 2 * tig;
            #pragma unroll
            for (int h = 0; h < 2; h++) {
                int m = m0 + wm + mi * 16 + gid + h * 8;
                if (m >= M) continue;
                #pragma unroll
                for (int e = 0; e < 2; e++) {
                    int n = cbase + e;
                    if (n >= N) continue;
                    float v = acc[mi][ni][h * 2 + e];
                    if (EPI == 3) v += bias[m];
                    else if (bias) v += bias[n];
                    if (EPI == 2) {
                        size_t so = (size_t)m * lds + n;
                        v += __bfloat162float(skH[so]) + __bfloat162float(skL[so]);
                    }
                    if (EPI >= 1) v = fmaxf(v, 0.f);
                    size_t off;
                    if (FLAT) {
                        if (TRANSOUT) {
                            int bb = m / MROWS;
                            int rr = m - bb * MROWS;
                            off = (size_t)bb * sC + (size_t)n * ldc + rr;
                        } else {
                            off = (size_t)m * ldc + n;
                        }
                    } else {
                        off = (size_t)bz * sC +
                              (TRANSOUT ? ((size_t)n * ldc + m) : ((size_t)m * ldc + n));
                    }
                    if (OUTF & 1) Cf[off] = v;
                    if (OUTF & 2) fsplit(v, &Ch[off], &Cl[off]);
                }
            }
        }
    }
}

// =============== fused GCN tail: h1 GEMM -> Y2 GEMM -> pooled partials ==========
__global__ void __launch_bounds__(256)
gcn_tail_k(const bf16* __restrict__ Ah, const bf16* __restrict__ Al,
           const bf16* __restrict__ Bh, const bf16* __restrict__ Bl,
           const float* __restrict__ bias,
           const bf16* __restrict__ Wh, const bf16* __restrict__ Wl,
           const float* __restrict__ rs, float* __restrict__ partial) {
    const int bz = blockIdx.z;
    Ah += (size_t)bz * S_HN; Al += (size_t)bz * S_HN;
    Bh += (size_t)bz * NSQ;  Bl += (size_t)bz * NSQ;
    const int n0 = blockIdx.x * BN;
    const int N = NN, K = NN;

    extern __shared__ bf16 dsm[];
    uint32_t smA = (uint32_t)__cvta_generic_to_shared(dsm);
    uint32_t smB = smA + 2 * ASTG;

    int tid = threadIdx.x;
    int warp = tid >> 5, lane = tid & 31;
    int wm = (warp >> 1) * 32;
    int wn = (warp & 1) * 32;
    int gid = lane >> 2, tig = lane & 3;

    const bf16* aSrc[4]; uint32_t aDst[4]; int aC[4];
    #pragma unroll
    for (int it = 0; it < 4; it++) {
        int idx = tid + it * 256;
        int buf = idx >> 9;
        int rem = idx & 511;
        int r = rem >> 2, c = (rem & 3) * 8;
        aC[it] = c;
        aSrc[it] = (buf ? Al : Ah) + (size_t)r * NN + c;
        aDst[it] = smA + buf * ABUF + (r * BKP + c) * 2;
    }
    const bf16* bSrc[2]; uint32_t bDst[2]; bool bPn[2]; int bR[2];
    #pragma unroll
    for (int it = 0; it < 2; it++) {
        int idx = tid + it * 256;
        int buf = idx >> 8;
        int rem = idx & 255;
        int r = rem >> 3, c = (rem & 7) * 8;
        bR[it] = r;
        bPn[it] = (n0 + c) < N;
        bSrc[it] = (buf ? Bl : Bh) + (size_t)r * NN + (n0 + (bPn[it] ? c : 0));
        bDst[it] = smB + buf * BBUF + (r * BNP + c) * 2;
    }

    auto issue = [&](int k0, int stg) {
        #pragma unroll
        for (int it = 0; it < 4; it++)
            cpa16(aDst[it] + stg * ASTG, aSrc[it] + k0, (k0 + aC[it] < K));
        #pragma unroll
        for (int it = 0; it < 2; it++)
            cpa16(bDst[it] + stg * BSTG, bSrc[it] + (size_t)k0 * NN,
                  bPn[it] && (k0 + bR[it] < K));
        cp_commit();
    };

    float acc[2][4][4] = {};
    uint32_t aB0 = smA + ((wm + (lane & 15)) * BKP + (lane >> 4) * 8) * 2;
    uint32_t bB0 = smB + ((lane & 15) * BNP + wn) * 2;

    int nk = (K + BK - 1) / BK;   // 13
    issue(0, 0);
    for (int t = 0; t < nk; t++) {
        if (t + 1 < nk) { issue((t + 1) * BK, (t + 1) & 1); cp_wait<1>(); }
        else cp_wait<0>();
        __syncthreads();
        int stg = t & 1;
        uint32_t aH = aB0 + stg * ASTG;
        uint32_t aL = aH + ABUF;
        uint32_t bH = bB0 + stg * BSTG;
        uint32_t bL = bH + BBUF;
        #pragma unroll
        for (int kc = 0; kc < 2; kc++) {
            uint32_t ah[2][4], al[2][4];
            ldm_x4(ah[0], aH + kc * 32);
            ldm_x4(ah[1], aH + 16 * BKP * 2 + kc * 32);
            ldm_x4(al[0], aL + kc * 32);
            ldm_x4(al[1], aL + 16 * BKP * 2 + kc * 32);
            #pragma unroll
            for (int ni = 0; ni < 4; ni++) {
                uint32_t bh[2], bl[2];
                ldm_x2t(bh, bH + kc * 16 * BNP * 2 + ni * 16);
                ldm_x2t(bl, bL + kc * 16 * BNP * 2 + ni * 16);
                #pragma unroll
                for (int mi = 0; mi < 2; mi++) {
                    mma16816(acc[mi][ni], ah[mi], bh);
                    mma16816(acc[mi][ni], al[mi], bh);
                    mma16816(acc[mi][ni], ah[mi], bl);
                }
            }
        }
        __syncthreads();
    }

    // phase 2: bias + relu, split h1 into smem [f=128][BNP]
    bf16* h1h = dsm;
    bf16* h1l = dsm + 128 * BNP;
    float* srs = (float*)(dsm + 2 * 128 * BNP);
    float* sacc = srs + 64;
    if (tid < 64) srs[tid] = (n0 + tid < N) ? rs[bz * NN + n0 + tid] : 0.f;
    #pragma unroll
    for (int mi = 0; mi < 2; mi++) {
        #pragma unroll
        for (int ni = 0; ni < 4; ni++) {
            int nlb = wn + ni * 8 + 2 * tig;
            #pragma unroll
            for (int h = 0; h < 2; h++) {
                int f = wm + mi * 16 + gid + h * 8;
                #pragma unroll
                for (int e = 0; e < 2; e++) {
                    int nl = nlb + e;
                    float v = fmaxf(acc[mi][ni][h * 2 + e] + bias[f], 0.f);
                    if (n0 + nl >= N) v = 0.f;
                    fsplit(v, &h1h[f * BNP + nl], &h1l[f * BNP + nl]);
                }
            }
        }
    }
    __syncthreads();

    // phase 3: Y2T tile = W2T @ h1T (K=128, A fragments from gmem)
    float acc2[2][4][4] = {};
    uint32_t h1hB = (uint32_t)__cvta_generic_to_shared(h1h);
    uint32_t h1lB = (uint32_t)__cvta_generic_to_shared(h1l);
    #pragma unroll
    for (int kk = 0; kk < 8; kk++) {
        int k0 = kk * 16;
        uint32_t ah2[2][4], al2[2][4];
        #pragma unroll
        for (int mi = 0; mi < 2; mi++) {
            int mrow = wm + mi * 16 + gid;
            const bf16* ph = Wh + mrow * HH + k0 + 2 * tig;
            const bf16* pl = Wl + mrow * HH + k0 + 2 * tig;
            ah2[mi][0] = *(const uint32_t*)ph;
            ah2[mi][1] = *(const uint32_t*)(ph + 8 * HH);
            ah2[mi][2] = *(const uint32_t*)(ph + 8);
            ah2[mi][3] = *(const uint32_t*)(ph + 8 * HH + 8);
            al2[mi][0] = *(const uint32_t*)pl;
            al2[mi][1] = *(const uint32_t*)(pl + 8 * HH);
            al2[mi][2] = *(const uint32_t*)(pl + 8);
            al2[mi][3] = *(const uint32_t*)(pl + 8 * HH + 8);
        }
        uint32_t bbh = h1hB + ((k0 + (lane & 15)) * BNP + wn) * 2;
        uint32_t bbl = h1lB + ((k0 + (lane & 15)) * BNP + wn) * 2;
        #pragma unroll
        for (int ni = 0; ni < 4; ni++) {
            uint32_t bh[2], bl[2];
            ldm_x2t(bh, bbh + ni * 16);
            ldm_x2t(bl, bbl + ni * 16);
            #pragma unroll
            for (int mi = 0; mi < 2; mi++) {
                mma16816(acc2[mi][ni], ah2[mi], bh);
                mma16816(acc2[mi][ni], al2[mi], bh);
                mma16816(acc2[mi][ni], ah2[mi], bl);
            }
        }
    }

    // phase 4: pooled partials
    #pragma unroll
    for (int mi = 0; mi < 2; mi++) {
        #pragma unroll
        for (int h = 0; h < 2; h++) {
            float p = 0.f;
            #pragma unroll
            for (int ni = 0; ni < 4; ni++)
                #pragma unroll
                for (int e = 0; e < 2; e++)
                    p += srs[wn + ni * 8 + 2 * tig + e] * acc2[mi][ni][h * 2 + e];
            p += __shfl_xor_sync(0xffffffffu, p, 1);
            p += __shfl_xor_sync(0xffffffffu, p, 2);
            if (tig == 0) {
                int g = wm + mi * 16 + gid + h * 8;
                sacc[(warp & 1) * 128 + g] = p;
            }
        }
    }
    __syncthreads();
    if (tid < 128)
        partial[((size_t)blockIdx.x * BATCH + bz) * HH + tid] = sacc[tid] + sacc[128 + tid];
}

// ---------------- final head ------------------------------------------------------
__global__ void head2_k(const float* __restrict__ partial, const float* __restrict__ b2,
                        const float* __restrict__ fcw, const float* __restrict__ fcb,
                        float* __restrict__ out) {
    int b = blockIdx.x;
    int f = threadIdx.x;
    __shared__ float sp[HH];
    float s = 0.f;
    #pragma unroll
    for (int t = 0; t < 7; t++) s += partial[((size_t)t * BATCH + b) * HH + f];
    sp[f] = fmaxf(s + b2[f], 0.f);
    __syncthreads();
    if (f < 2) {
        float o = fcb[f];
        for (int q = 0; q < HH; q++) o += sp[q] * fcw[q * 2 + f];
        out[b * 2 + f] = o;
    }
}

// -----------------------------------------------------------------------------------
extern "C" void kernel_launch(void* const* d_in, const int* in_sizes, int n_in,
                              void* d_out, int out_size) {
    const float* x      = (const float*)d_in[0];
    const float* enc1_w = (const float*)d_in[2];
    const float* enc1_b = (const float*)d_in[3];
    const float* enc2_w = (const float*)d_in[4];
    const float* enc2_b = (const float*)d_in[5];
    const float* dec2_w = (const float*)d_in[6];
    const float* dec2_b = (const float*)d_in[7];
    const float* dec1_w = (const float*)d_in[8];
    const float* dec1_b = (const float*)d_in[9];
    const float* gcn1_w = (const float*)d_in[10];
    const float* gcn1_b = (const float*)d_in[11];
    const float* gcn2_w = (const float*)d_in[12];
    const float* gcn2_b = (const float*)d_in[13];
    const float* fc_w   = (const float*)d_in[14];
    const float* fc_b   = (const float*)d_in[15];
    float* out = (float*)d_out;

    float *xf, *delta, *degp, *part, *rs;
    bf16 *ah, *al, *anh, *anl, *o1h, *o1l, *o2ah, *o2al, *o2th, *o2tl;
    bf16 *y1h, *y1l, *wh, *wl;
    ull* thresh;
    cudaGetSymbolAddress((void**)&xf, g_xf);
    cudaGetSymbolAddress((void**)&delta, g_delta);
    cudaGetSymbolAddress((void**)&degp, g_degp);
    cudaGetSymbolAddress((void**)&part, g_part);
    cudaGetSymbolAddress((void**)&ah, g_ah);
    cudaGetSymbolAddress((void**)&al, g_al);
    cudaGetSymbolAddress((void**)&anh, g_anh);
    cudaGetSymbolAddress((void**)&anl, g_anl);
    cudaGetSymbolAddress((void**)&o1h, g_o1h);
    cudaGetSymbolAddress((void**)&o1l, g_o1l);
    cudaGetSymbolAddress((void**)&o2ah, g_o2ah);
    cudaGetSymbolAddress((void**)&o2al, g_o2al);
    cudaGetSymbolAddress((void**)&o2th, g_o2th);
    cudaGetSymbolAddress((void**)&o2tl, g_o2tl);
    cudaGetSymbolAddress((void**)&y1h, g_y1h);
    cudaGetSymbolAddress((void**)&y1l, g_y1l);
    cudaGetSymbolAddress((void**)&wh, g_wh);
    cudaGetSymbolAddress((void**)&wl, g_wl);
    cudaGetSymbolAddress((void**)&thresh, g_thresh);
    cudaGetSymbolAddress((void**)&rs, g_rs);

    cudaFuncSetAttribute((const void*)&bgemm_k<1,1,2,1>, cudaFuncAttributeMaxDynamicSharedMemorySize, SMEM_TOT);
    cudaFuncSetAttribute((const void*)&bgemm_k<1,0,2,1>, cudaFuncAttributeMaxDynamicSharedMemorySize, SMEM_TOT);
    cudaFuncSetAttribute((const void*)&bgemm_k<2,1,2,1>, cudaFuncAttributeMaxDynamicSharedMemorySize, SMEM_TOT);
    cudaFuncSetAttribute((const void*)&bgemm_k<0,0,1,1>, cudaFuncAttributeMaxDynamicSharedMemorySize, SMEM_TOT);
    cudaFuncSetAttribute((const void*)&bgemm_k<0,1,2,1>, cudaFuncAttributeMaxDynamicSharedMemorySize, SMEM_TOT);
    cudaFuncSetAttribute((const void*)&gcn_tail_k, cudaFuncAttributeMaxDynamicSharedMemorySize, SMEM_TOT);
    cudaFuncSetAttribute((const void*)&radix_select_k, cudaFuncAttributeMaxDynamicSharedMemorySize, 49152);

    static cudaStream_t s2 = nullptr;
    static cudaEvent_t evA = nullptr, evB = nullptr, evC = nullptr, evD = nullptr;
    if (!s2) {
        cudaStreamCreateWithFlags(&s2, cudaStreamNonBlocking);
        cudaEventCreateWithFlags(&evA, cudaEventDisableTiming);
        cudaEventCreateWithFlags(&evB, cudaEventDisableTiming);
        cudaEventCreateWithFlags(&evC, cudaEventDisableTiming);
        cudaEventCreateWithFlags(&evD, cudaEventDisableTiming);
    }

    // ---- fork 1: single combined weight split on s2, fisher on main ----
    cudaEventRecord(evA, 0);
    cudaStreamWaitEvent(s2, evA, 0);
    wsplit_all_k<<<dim3(200, 6), 256, 0, s2>>>(
        enc1_w, enc2_w, dec2_w, dec1_w, gcn1_w, gcn2_w, wh, wl);
    cudaEventRecord(evB, s2);

    fisher_k<<<dim3(157, BATCH), 256>>>(x, ah, al);
    cudaStreamWaitEvent(0, evB, 0);

    // 1) out1 = relu(xf @ enc1_w + b) -> split [H][N] per batch, flat M=51200
    bgemm_k<1, 1, 2, 1><<<dim3(2, 400), 256, SMEM_TOT>>>(
        ah, al, 0, NN, wh + W_E1, wl + W_E1, 0, HH, enc1_b,
        nullptr, nullptr, 0, nullptr, o1h, o1l, S_HN, NN, BATCH * NN, HH, NN, NN);

    // 2) out2a = relu(out1 @ enc2_w + b), flat M=16384
    bgemm_k<1, 0, 2, 1><<<dim3(2, 128), 256, SMEM_TOT>>>(
        o1h, o1l, 0, NN, wh + W_E2, wl + W_E2, 0, HH, enc2_b,
        nullptr, nullptr, 0, nullptr, o2ah, o2al, S_HH, HH, BATCH * HH, HH, NN, HH);

    // 3) out2 = relu(out2a @ dec2_w + b + out1[skip pair]) -> out2T split
    bgemm_k<2, 1, 2, 1><<<dim3(7, 128), 256, SMEM_TOT>>>(
        o2ah, o2al, 0, HH, wh + W_D2, wl + W_D2, 0, NN, dec2_b,
        o1h, o1l, NN, nullptr, o2th, o2tl, S_HN, HH, BATCH * HH, NN, HH, HH);

    // 4) delta = out2T @ dec1_w + b, flat M=51200, fp32
    bgemm_k<0, 0, 1, 1><<<dim3(7, 400), 256, SMEM_TOT>>>(
        o2th, o2tl, 0, HH, wh + W_D1, wl + W_D1, 0, NN, dec1_b,
        nullptr, nullptr, 0, delta, nullptr, nullptr, NSQ, NN, BATCH * NN, NN, HH, NN);

    // 5) x2 = xf_split + sym(delta)
    sym2_k<<<dim3(91, BATCH), dim3(8, 32)>>>(xf, delta, ah, al);

    // ---- fork 2: Y1 GEMM on s2, selection chain on main ----
    cudaEventRecord(evC, 0);
    cudaStreamWaitEvent(s2, evC, 0);
    bgemm_k<0, 1, 2, 1><<<dim3(2, 400), 256, SMEM_TOT, s2>>>(
        ah, al, 0, NN, wh + W_G1, wl + W_G1, 0, HH, nullptr,
        nullptr, nullptr, 0, nullptr, y1h, y1l, S_HN, NN, BATCH * NN, HH, NN, NN);
    cudaEventRecord(evD, s2);

    // 6) top-k threshold (1024 threads/CTA)
    radix_select_k<<<BATCH, RNT, 49152>>>(xf, thresh);

    // 7) masked column degree partials (float4)
    degp_k<<<dim3(4, BATCH), 128>>>(xf, thresh, degp);

    // 8) warp-per-row An split + row means (dinv in-kernel)
    an_k<<<dim3(50, BATCH), 256>>>(xf, thresh, degp, anh, anl, rs);

    cudaStreamWaitEvent(0, evD, 0);

    // 9) fused GCN tail: h1 -> Y2 -> pooled partials
    gcn_tail_k<<<dim3(7, 1, BATCH), 256, SMEM_TOT>>>(
        y1h, y1l, anh, anl, gcn1_b, wh + W_G2T, wl + W_G2T, rs, part);

    // 10) final head
    head2_k<<<BATCH, 128>>>(part, gcn2_b, fc_w, fc_b, out);
}

// round 16
// speedup vs baseline: 1.0233x; 1.0233x over previous
#include <cuda_runtime.h>
#include <cuda_bf16.h>
#include <cstdint>

#define EPS 1e-9f
#define BATCH 128
#define NN 400
#define HH 128
#define NSQ (NN * NN)          // 160000
#define NQ4 (NSQ / 4)          // 40000
#define S_HN (HH * NN)         // 51200
#define S_HH (HH * HH)         // 16384
#define KTOP 32000

typedef __nv_bfloat16 bf16;
typedef unsigned long long ull;

// ---------------- scratch -----------------------------------------------------
__device__ float g_xf[BATCH * NSQ];                        // x2 fp32 (written by sym)
__device__ float g_delta[BATCH * NSQ];
__device__ float g_degp[BATCH * 4 * NN];
__device__ float g_part[7 * BATCH * HH];
__device__ bf16 g_ah[BATCH * NSQ], g_al[BATCH * NSQ];
__device__ bf16 g_anh[BATCH * NSQ], g_anl[BATCH * NSQ];
__device__ bf16 g_o1h[BATCH * S_HN], g_o1l[BATCH * S_HN];
__device__ bf16 g_o2ah[BATCH * S_HH], g_o2al[BATCH * S_HH];
__device__ bf16 g_o2th[BATCH * S_HN], g_o2tl[BATCH * S_HN];
__device__ bf16 g_y1h[BATCH * S_HN], g_y1l[BATCH * S_HN];
__device__ bf16 g_wh[272384], g_wl[272384];
__device__ ull g_thresh[BATCH];
__device__ float g_rs[BATCH * NN];

#define W_E1 0
#define W_E2 51200
#define W_D2 102400
#define W_D1 153600
#define W_G1 204800
#define W_G2T 256000

__device__ __forceinline__ void fsplit(float v, bf16* h, bf16* l) {
    bf16 hh = __float2bfloat16(v);
    *h = hh;
    *l = __float2bfloat16(v - __bfloat162float(hh));
}
__device__ __forceinline__ void fsplit4(const float* v, uint2* ph, uint2* pl) {
    unsigned short h[4], l[4];
    #pragma unroll
    for (int e = 0; e < 4; e++) {
        bf16 hh = __float2bfloat16(v[e]);
        h[e] = __bfloat16_as_ushort(hh);
        l[e] = __bfloat16_as_ushort(__float2bfloat16(v[e] - __bfloat162float(hh)));
    }
    ph->x = (unsigned)h[0] | ((unsigned)h[1] << 16);
    ph->y = (unsigned)h[2] | ((unsigned)h[3] << 16);
    pl->x = (unsigned)l[0] | ((unsigned)l[1] << 16);
    pl->y = (unsigned)l[2] | ((unsigned)l[3] << 16);
}
__device__ __forceinline__ void unsplit4(uint2 ph, uint2 pl, float* v) {
    v[0] = __uint_as_float(ph.x << 16) + __uint_as_float(pl.x << 16);
    v[1] = __uint_as_float(ph.x & 0xffff0000u) + __uint_as_float(pl.x & 0xffff0000u);
    v[2] = __uint_as_float(ph.y << 16) + __uint_as_float(pl.y << 16);
    v[3] = __uint_as_float(ph.y & 0xffff0000u) + __uint_as_float(pl.y & 0xffff0000u);
}

// ---------------- weight prep --------------------------------------------------
__global__ void wsplit_k(const float* __restrict__ w, bf16* __restrict__ h,
                         bf16* __restrict__ l, int n) {
    int i = blockIdx.x * 256 + threadIdx.x;
    if (i < n) fsplit(w[i], &h[i], &l[i]);
}
__global__ void wtsplit_k(const float* __restrict__ w, bf16* __restrict__ h,
                          bf16* __restrict__ l) {
    int i = blockIdx.x * 256 + threadIdx.x;
    int g = i >> 7, f = i & 127;
    fsplit(w[f * HH + g], &h[i], &l[i]);
}

// ---------------- fisher -> bf16 split (MUFU __logf) ------------------------------
__global__ void fisher_k(const float* __restrict__ x,
                         bf16* __restrict__ xh, bf16* __restrict__ xl) {
    int t = blockIdx.x * 256 + threadIdx.x;
    int b = blockIdx.y;
    if (t >= NQ4) return;
    size_t base = (size_t)b * NSQ;
    float x00 = x[base];
    float d = 0.5f * __logf((1.f + x00 + EPS) / (1.f - x00 + EPS));
    float rd = 1.f / d;
    float4 v = ((const float4*)(x + base))[t];
    float o[4];
    o[0] = 0.5f * __logf((1.f + v.x + EPS) / (1.f - v.x + EPS)) * rd;
    o[1] = 0.5f * __logf((1.f + v.y + EPS) / (1.f - v.y + EPS)) * rd;
    o[2] = 0.5f * __logf((1.f + v.z + EPS) / (1.f - v.z + EPS)) * rd;
    o[3] = 0.5f * __logf((1.f + v.w + EPS) / (1.f - v.w + EPS)) * rd;
    uint2 ph, pl;
    fsplit4(o, &ph, &pl);
    ((uint2*)(xh + base))[t] = ph;
    ((uint2*)(xl + base))[t] = pl;
}

// ---------------- symmetric-pair symmetrize: x2 fp32 + split ---------------------
__global__ void sym2_k(float* __restrict__ x2, const float* __restrict__ delta,
                       bf16* __restrict__ xh, bf16* __restrict__ xl) {
    int b = blockIdx.y;
    int p = blockIdx.x;
    int ti = 0, rem = p;
    while (rem >= 13 - ti) { rem -= 13 - ti; ti++; }
    int tj = ti + rem;
    int i0 = ti * 32, j0 = tj * 32;
    int tx = threadIdx.x, ty = threadIdx.y;
    __shared__ float shA[32][33];
    __shared__ float shB[32][33];
    size_t base = (size_t)b * NSQ;
    bool diag = (ti == tj);

    {
        int r = i0 + ty, c = j0 + tx * 4;
        float4 v = make_float4(0.f, 0.f, 0.f, 0.f);
        if (r < NN && c < NN) v = *(const float4*)&delta[base + (size_t)r * NN + c];
        shA[ty][tx * 4 + 0] = v.x; shA[ty][tx * 4 + 1] = v.y;
        shA[ty][tx * 4 + 2] = v.z; shA[ty][tx * 4 + 3] = v.w;
    }
    if (!diag) {
        int r = j0 + ty, c = i0 + tx * 4;
        float4 v = make_float4(0.f, 0.f, 0.f, 0.f);
        if (r < NN && c < NN) v = *(const float4*)&delta[base + (size_t)r * NN + c];
        shB[ty][tx * 4 + 0] = v.x; shB[ty][tx * 4 + 1] = v.y;
        shB[ty][tx * 4 + 2] = v.z; shB[ty][tx * 4 + 3] = v.w;
    }
    __syncthreads();

    {
        int r = i0 + ty, c0 = j0 + tx * 4;
        if (r < NN && c0 < NN) {
            size_t idx = base + (size_t)r * NN + c0;
            float o[4];
            unsplit4(*(const uint2*)&xh[idx], *(const uint2*)&xl[idx], o);
            #pragma unroll
            for (int e = 0; e < 4; e++) {
                int c = c0 + e;
                float dT = diag ? shA[tx * 4 + e][ty] : shB[tx * 4 + e][ty];
                if (r != c) o[e] += 0.5f * (shA[ty][tx * 4 + e] + dT);
            }
            *(float4*)&x2[idx] = make_float4(o[0], o[1], o[2], o[3]);
            uint2 ph, pl;
            fsplit4(o, &ph, &pl);
            *(uint2*)&xh[idx] = ph;
            *(uint2*)&xl[idx] = pl;
        }
    }
    if (!diag) {
        int r = j0 + ty, c0 = i0 + tx * 4;
        if (r < NN && c0 < NN) {
            size_t idx = base + (size_t)r * NN + c0;
            float o[4];
            unsplit4(*(const uint2*)&xh[idx], *(const uint2*)&xl[idx], o);
            #pragma unroll
            for (int e = 0; e < 4; e++) {
                int c = c0 + e;
                if (r != c) o[e] += 0.5f * (shB[ty][tx * 4 + e] + shA[tx * 4 + e][ty]);
            }
            *(float4*)&x2[idx] = make_float4(o[0], o[1], o[2], o[3]);
            uint2 ph, pl;
            fsplit4(o, &ph, &pl);
            *(uint2*)&xh[idx] = ph;
            *(uint2*)&xl[idx] = pl;
        }
    }
}

// ---------------- keys ------------------------------------------------------------
__device__ __forceinline__ unsigned make_vkey(float v) {
    unsigned u = __float_as_uint(v);
    return (u & 0x80000000u) ? ~u : (u | 0x80000000u);
}
__device__ __forceinline__ ull make_key(float v, unsigned t) {
    return ((ull)make_vkey(v) << 32) | (ull)(~t);
}

// ---------------- exact top-k: two 12-bit passes, 1024 threads --------------------
#define RNT 1024
__global__ void radix_select_k(const float* __restrict__ x2,
                               ull* __restrict__ thresh) {
    const int b = blockIdx.x;
    const float4* xp4 = (const float4*)(x2 + (size_t)b * NSQ);
    extern __shared__ unsigned rsm[];
    unsigned* hist = rsm;                 // [2][4096]
    ull* buf = (ull*)(rsm + 8192);        // [2048]
    __shared__ unsigned wsum[32];
    __shared__ unsigned s_bin, s_rem, s_cnt;
    int tid = threadIdx.x;
    int lane = tid & 31, wid = tid >> 5;
    int hsel = (wid & 1) * 4096;
    if (tid == 0) { s_rem = KTOP; s_cnt = 0; }

    unsigned b1 = 0;
    #pragma unroll
    for (int pass = 0; pass < 2; pass++) {
        for (int i = tid; i < 8192; i += RNT) hist[i] = 0;
        __syncthreads();
        for (int t = tid; t < 40960; t += RNT) {
            bool inr = t < NQ4;
            float4 v = inr ? xp4[t] : make_float4(0.f, 0.f, 0.f, 0.f);
            float vv[4] = {v.x, v.y, v.z, v.w};
            #pragma unroll
            for (int e = 0; e < 4; e++) {
                unsigned vk = make_vkey(vv[e]);
                bool ok = inr && (pass == 0 || (vk >> 20) == b1);
                unsigned bin = (pass == 0) ? (vk >> 20) : ((vk >> 8) & 4095);
                unsigned active = __ballot_sync(0xffffffffu, ok);
                if (ok) {
                    unsigned peers = __match_any_sync(active, bin);
                    int leader = __ffs(peers) - 1;
                    if (lane == leader) atomicAdd(&hist[hsel + bin], __popc(peers));
                }
            }
        }
        __syncthreads();
        unsigned cs = 0;
        #pragma unroll
        for (int k = 0; k < 4; k++) {
            int bin = 4095 - 4 * tid - k;
            cs += hist[bin] + hist[4096 + bin];
        }
        unsigned v = cs;
        #pragma unroll
        for (int o = 1; o < 32; o <<= 1) {
            unsigned u = __shfl_up_sync(0xffffffffu, v, o);
            if (lane >= o) v += u;
        }
        if (lane == 31) wsum[wid] = v;
        __syncthreads();
        if (wid == 0) {
            unsigned w = wsum[lane];
            #pragma unroll
            for (int o = 1; o < 32; o <<= 1) {
                unsigned u = __shfl_up_sync(0xffffffffu, w, o);
                if (lane >= o) w += u;
            }
            wsum[lane] = w;
        }
        __syncthreads();
        unsigned incl = v + (wid ? wsum[wid - 1] : 0);
        unsigned excl = incl - cs;
        unsigned rem = s_rem;
        if (rem > excl && rem <= incl) {
            unsigned c = excl;
            #pragma unroll
            for (int k = 0; k < 4; k++) {
                int bin = 4095 - 4 * tid - k;
                unsigned bc = hist[bin] + hist[4096 + bin];
                if (rem <= c + bc) { s_bin = (unsigned)bin; s_rem = rem - c; break; }
                c += bc;
            }
        }
        __syncthreads();
        if (pass == 0) b1 = s_bin;
    }
    unsigned pref24 = (b1 << 12) | s_bin;
    unsigned remf = s_rem;

    for (int t = tid; t < NQ4; t += RNT) {
        float4 v = xp4[t];
        float vv[4] = {v.x, v.y, v.z, v.w};
        #pragma unroll
        for (int e = 0; e < 4; e++) {
            if ((make_vkey(vv[e]) >> 8) == pref24) {
                unsigned p = atomicAdd(&s_cnt, 1);
                if (p < 2048) buf[p] = make_key(vv[e], (unsigned)(t * 4 + e));
            }
        }
    }
    __syncthreads();
    unsigned n = min(s_cnt, 2048u);
    for (int t = tid; t < (int)n; t += RNT) {
        ull k = buf[t];
        unsigned c = 0;
        for (unsigned j = 0; j < n; j++) c += (buf[j] > k);
        if (c == remf - 1) thresh[b] = k;
    }
}

// ---------------- fused mask + partial column degrees ----------------------------
__global__ void degp_k(const float* __restrict__ x2, const ull* __restrict__ th,
                       float* __restrict__ part) {
    int q = blockIdx.x, b = blockIdx.y;
    int j = threadIdx.x;
    if (j >= NN) return;
    ull thr = th[b];
    const float* xb = x2 + (size_t)b * NSQ;
    float acc = 0.f;
    int i0 = q * 100;
    #pragma unroll 4
    for (int i = i0; i < i0 + 100; i++) {
        float v = xb[(size_t)i * NN + j];
        unsigned r = (unsigned)(i * NN + j);
        float a = (make_key(v, r) >= thr) ? v : 0.f;
        if (i == j && a == 0.f) a = 1.f;
        acc += a;
    }
    part[((size_t)b * 4 + q) * NN + j] = acc;
}

// ------- warp-per-row: dinv (from partials) + mask + An split + row means --------
__global__ void __launch_bounds__(256)
an_k(const float* __restrict__ x2, const ull* __restrict__ th,
     const float* __restrict__ part,
     bf16* __restrict__ anh, bf16* __restrict__ anl,
     float* __restrict__ rs) {
    int b = blockIdx.y;
    int tid = threadIdx.x;
    __shared__ float sdv[NN];
    {
        size_t base = (size_t)b * 4 * NN;
        for (int j = tid; j < NN; j += 256) {
            float s = part[base + j] + part[base + NN + j]
                    + part[base + 2 * NN + j] + part[base + 3 * NN + j];
            float dv = rsqrtf(s);
            if (isinf(dv)) dv = 0.f;
            sdv[j] = dv;
        }
    }
    __syncthreads();
    int warp = tid >> 5, lane = tid & 31;
    int i = blockIdx.x * 8 + warp;
    ull thr = th[b];
    size_t roff = (size_t)b * NSQ + (size_t)i * NN;
    float di = sdv[i];
    float acc = 0.f;
    for (int c = lane; c < 100; c += 32) {
        int j0 = c * 4;
        float4 v = *(const float4*)&x2[roff + j0];
        float vv[4] = {v.x, v.y, v.z, v.w};
        float w[4];
        #pragma unroll
        for (int e = 0; e < 4; e++) {
            unsigned r = (unsigned)(i * NN + j0 + e);
            float a = (make_key(vv[e], r) >= thr) ? vv[e] : 0.f;
            if (i == j0 + e && a == 0.f) a = 1.f;
            w[e] = a * di * sdv[j0 + e];
            acc += w[e];
        }
        uint2 ph, pl;
        fsplit4(w, &ph, &pl);
        *(uint2*)&anh[roff + j0] = ph;
        *(uint2*)&anl[roff + j0] = pl;
    }
    #pragma unroll
    for (int o = 16; o > 0; o >>= 1) acc += __shfl_xor_sync(0xffffffffu, acc, o);
    if (lane == 0) rs[b * NN + i] = acc * (1.f / NN);
}

// =============== 2-stage cp.async bf16 split GEMM ================================
#define BM 128
#define BN 64
#define BK 32
#define BKP 40
#define BNP 72
#define ABUF (BM * BKP * 2)
#define ASTG (2 * ABUF)
#define BBUF (BK * BNP * 2)
#define BSTG (2 * BBUF)
#define SMEM_TOT (2 * (ASTG + BSTG))   // 59392 -> 3 CTAs/SM

__device__ __forceinline__ void ldm_x4(uint32_t* r, uint32_t a) {
    asm volatile("ldmatrix.sync.aligned.m8n8.x4.shared.b16 {%0,%1,%2,%3}, [%4];"
        : "=r"(r[0]), "=r"(r[1]), "=r"(r[2]), "=r"(r[3]) : "r"(a));
}
__device__ __forceinline__ void ldm_x2t(uint32_t* r, uint32_t a) {
    asm volatile("ldmatrix.sync.aligned.m8n8.x2.trans.shared.b16 {%0,%1}, [%2];"
        : "=r"(r[0]), "=r"(r[1]) : "r"(a));
}
__device__ __forceinline__ void mma16816(float* d, const uint32_t* a, const uint32_t* b) {
    asm volatile("mma.sync.aligned.m16n8k16.row.col.f32.bf16.bf16.f32 "
        "{%0,%1,%2,%3}, {%4,%5,%6,%7}, {%8,%9}, {%0,%1,%2,%3};"
        : "+f"(d[0]), "+f"(d[1]), "+f"(d[2]), "+f"(d[3])
        : "r"(a[0]), "r"(a[1]), "r"(a[2]), "r"(a[3]), "r"(b[0]), "r"(b[1]));
}
__device__ __forceinline__ void cpa16(uint32_t dst, const bf16* src, bool p) {
    int sz = p ? 16 : 0;
    asm volatile("cp.async.cg.shared.global [%0], [%1], 16, %2;"
        :: "r"(dst), "l"(src), "r"(sz));
}
__device__ __forceinline__ void cp_commit() {
    asm volatile("cp.async.commit_group;");
}
template<int W> __device__ __forceinline__ void cp_wait() {
    asm volatile("cp.async.wait_group %0;" :: "n"(W));
}

// EPI: 0 none, 1 relu+bias[n], 2 relu+bias[n]+skip(bf16 pair), 3 relu+bias[m]
// OUTF bit0: fp32 C; bit1: split bf16 C. FLAT: batch folded into M.
template<int EPI, int TRANSOUT, int OUTF, int FLAT>
__global__ void __launch_bounds__(256)
bgemm_k(const bf16* __restrict__ Ah, const bf16* __restrict__ Al, size_t sA, int lda,
        const bf16* __restrict__ Bh, const bf16* __restrict__ Bl, size_t sB, int ldb,
        const float* __restrict__ bias,
        const bf16* __restrict__ skH, const bf16* __restrict__ skL, int lds,
        float* __restrict__ Cf, bf16* __restrict__ Ch, bf16* __restrict__ Cl,
        size_t sC, int ldc, int M, int N, int K, int MROWS) {
    int bz = FLAT ? 0 : blockIdx.z;
    if (!FLAT) {
        Ah += (size_t)bz * sA; Al += (size_t)bz * sA;
        Bh += (size_t)bz * sB; Bl += (size_t)bz * sB;
    }

    int n0 = blockIdx.x * BN;
    int m0 = blockIdx.y * BM;

    extern __shared__ bf16 dsm[];
    uint32_t smA = (uint32_t)__cvta_generic_to_shared(dsm);
    uint32_t smB = smA + 2 * ASTG;

    int tid = threadIdx.x;
    int warp = tid >> 5, lane = tid & 31;
    int wm = (warp >> 1) * 32;
    int wn = (warp & 1) * 32;
    int gid = lane >> 2, tig = lane & 3;

    const bf16* aSrc[4]; uint32_t aDst[4]; bool aPm[4]; int aC[4];
    #pragma unroll
    for (int it = 0; it < 4; it++) {
        int idx = tid + it * 256;
        int buf = idx >> 9;
        int rem = idx & 511;
        int r = rem >> 2, c = (rem & 3) * 8;
        int m = m0 + r;
        aPm[it] = m < M;
        aC[it] = c;
        aSrc[it] = (buf ? Al : Ah) + (size_t)(aPm[it] ? m : (M - 1)) * lda + c;
        aDst[it] = smA + buf * ABUF + (r * BKP + c) * 2;
    }
    const bf16* bSrc[2]; uint32_t bDst[2]; bool bPn[2]; int bR[2];
    #pragma unroll
    for (int it = 0; it < 2; it++) {
        int idx = tid + it * 256;
        int buf = idx >> 8;
        int rem = idx & 255;
        int r = rem >> 3, c = (rem & 7) * 8;
        bR[it] = r;
        bPn[it] = (n0 + c) < N;
        bSrc[it] = (buf ? Bl : Bh) + (size_t)r * ldb + (n0 + (bPn[it] ? c : 0));
        bDst[it] = smB + buf * BBUF + (r * BNP + c) * 2;
    }

    auto issue = [&](int k0, int stg) {
        #pragma unroll
        for (int it = 0; it < 4; it++)
            cpa16(aDst[it] + stg * ASTG, aSrc[it] + k0, aPm[it] && (k0 + aC[it] < K));
        #pragma unroll
        for (int it = 0; it < 2; it++)
            cpa16(bDst[it] + stg * BSTG, bSrc[it] + (size_t)k0 * ldb,
                  bPn[it] && (k0 + bR[it] < K));
        cp_commit();
    };

    float acc[2][4][4] = {};

    uint32_t aB0 = smA + ((wm + (lane & 15)) * BKP + (lane >> 4) * 8) * 2;
    uint32_t bB0 = smB + ((lane & 15) * BNP + wn) * 2;

    int nk = (K + BK - 1) / BK;
    issue(0, 0);
    for (int t = 0; t < nk; t++) {
        if (t + 1 < nk) { issue((t + 1) * BK, (t + 1) & 1); cp_wait<1>(); }
        else cp_wait<0>();
        __syncthreads();
        int stg = t & 1;
        uint32_t aH = aB0 + stg * ASTG;
        uint32_t aL = aH + ABUF;
        uint32_t bH = bB0 + stg * BSTG;
        uint32_t bL = bH + BBUF;
        #pragma unroll
        for (int kc = 0; kc < 2; kc++) {
            uint32_t ah[2][4], al[2][4];
            ldm_x4(ah[0], aH + kc * 32);
            ldm_x4(ah[1], aH + 16 * BKP * 2 + kc * 32);
            ldm_x4(al[0], aL + kc * 32);
            ldm_x4(al[1], aL + 16 * BKP * 2 + kc * 32);
            #pragma unroll
            for (int ni = 0; ni < 4; ni++) {
                uint32_t bh[2], bl[2];
                ldm_x2t(bh, bH + kc * 16 * BNP * 2 + ni * 16);
                ldm_x2t(bl, bL + kc * 16 * BNP * 2 + ni * 16);
                #pragma unroll
                for (int mi = 0; mi < 2; mi++) {
                    mma16816(acc[mi][ni], ah[mi], bh);
                    mma16816(acc[mi][ni], al[mi], bh);
                    mma16816(acc[mi][ni], ah[mi], bl);
                }
            }
        }
        __syncthreads();
    }

    #pragma unroll
    for (int mi = 0; mi < 2; mi++) {
        #pragma unroll
        for (int ni = 0; ni < 4; ni++) {
            int cbase = n0 + wn + ni * 8 + 2 * tig;
            #pragma unroll
            for (int h = 0; h < 2; h++) {
                int m = m0 + wm + mi * 16 + gid + h * 8;
                if (m >= M) continue;
                #pragma unroll
                for (int e = 0; e < 2; e++) {
                    int n = cbase + e;
                    if (n >= N) continue;
                    float v = acc[mi][ni][h * 2 + e];
                    if (EPI == 3) v += bias[m];
                    else if (bias) v += bias[n];
                    if (EPI == 2) {
                        size_t so = (size_t)m * lds + n;
                        v += __bfloat162float(skH[so]) + __bfloat162float(skL[so]);
                    }
                    if (EPI >= 1) v = fmaxf(v, 0.f);
                    size_t off;
                    if (FLAT) {
                        if (TRANSOUT) {
                            int bb = m / MROWS;
                            int rr = m - bb * MROWS;
                            off = (size_t)bb * sC + (size_t)n * ldc + rr;
                        } else {
                            off = (size_t)m * ldc + n;
                        }
                    } else {
                        off = (size_t)bz * sC +
                              (TRANSOUT ? ((size_t)n * ldc + m) : ((size_t)m * ldc + n));
                    }
                    if (OUTF & 1) Cf[off] = v;
                    if (OUTF & 2) fsplit(v, &Ch[off], &Cl[off]);
                }
            }
        }
    }
}

// =============== fused GCN tail: h1 GEMM -> Y2 GEMM -> pooled partials ==========
__global__ void __launch_bounds__(256)
gcn_tail_k(const bf16* __restrict__ Ah, const bf16* __restrict__ Al,
           const bf16* __restrict__ Bh, const bf16* __restrict__ Bl,
           const float* __restrict__ bias,
           const bf16* __restrict__ Wh, const bf16* __restrict__ Wl,
           const float* __restrict__ rs, float* __restrict__ partial) {
    const int bz = blockIdx.z;
    Ah += (size_t)bz * S_HN; Al += (size_t)bz * S_HN;
    Bh += (size_t)bz * NSQ;  Bl += (size_t)bz * NSQ;
    const int n0 = blockIdx.x * BN;
    const int N = NN, K = NN;

    extern __shared__ bf16 dsm[];
    uint32_t smA = (uint32_t)__cvta_generic_to_shared(dsm);
    uint32_t smB = smA + 2 * ASTG;

    int tid = threadIdx.x;
    int warp = tid >> 5, lane = tid & 31;
    int wm = (warp >> 1) * 32;
    int wn = (warp & 1) * 32;
    int gid = lane >> 2, tig = lane & 3;

    const bf16* aSrc[4]; uint32_t aDst[4]; int aC[4];
    #pragma unroll
    for (int it = 0; it < 4; it++) {
        int idx = tid + it * 256;
        int buf = idx >> 9;
        int rem = idx & 511;
        int r = rem >> 2, c = (rem & 3) * 8;
        aC[it] = c;
        aSrc[it] = (buf ? Al : Ah) + (size_t)r * NN + c;
        aDst[it] = smA + buf * ABUF + (r * BKP + c) * 2;
    }
    const bf16* bSrc[2]; uint32_t bDst[2]; bool bPn[2]; int bR[2];
    #pragma unroll
    for (int it = 0; it < 2; it++) {
        int idx = tid + it * 256;
        int buf = idx >> 8;
        int rem = idx & 255;
        int r = rem >> 3, c = (rem & 7) * 8;
        bR[it] = r;
        bPn[it] = (n0 + c) < N;
        bSrc[it] = (buf ? Bl : Bh) + (size_t)r * NN + (n0 + (bPn[it] ? c : 0));
        bDst[it] = smB + buf * BBUF + (r * BNP + c) * 2;
    }

    auto issue = [&](int k0, int stg) {
        #pragma unroll
        for (int it = 0; it < 4; it++)
            cpa16(aDst[it] + stg * ASTG, aSrc[it] + k0, (k0 + aC[it] < K));
        #pragma unroll
        for (int it = 0; it < 2; it++)
            cpa16(bDst[it] + stg * BSTG, bSrc[it] + (size_t)k0 * NN,
                  bPn[it] && (k0 + bR[it] < K));
        cp_commit();
    };

    float acc[2][4][4] = {};
    uint32_t aB0 = smA + ((wm + (lane & 15)) * BKP + (lane >> 4) * 8) * 2;
    uint32_t bB0 = smB + ((lane & 15) * BNP + wn) * 2;

    int nk = (K + BK - 1) / BK;   // 13
    issue(0, 0);
    for (int t = 0; t < nk; t++) {
        if (t + 1 < nk) { issue((t + 1) * BK, (t + 1) & 1); cp_wait<1>(); }
        else cp_wait<0>();
        __syncthreads();
        int stg = t & 1;
        uint32_t aH = aB0 + stg * ASTG;
        uint32_t aL = aH + ABUF;
        uint32_t bH = bB0 + stg * BSTG;
        uint32_t bL = bH + BBUF;
        #pragma unroll
        for (int kc = 0; kc < 2; kc++) {
            uint32_t ah[2][4], al[2][4];
            ldm_x4(ah[0], aH + kc * 32);
            ldm_x4(ah[1], aH + 16 * BKP * 2 + kc * 32);
            ldm_x4(al[0], aL + kc * 32);
            ldm_x4(al[1], aL + 16 * BKP * 2 + kc * 32);
            #pragma unroll
            for (int ni = 0; ni < 4; ni++) {
                uint32_t bh[2], bl[2];
                ldm_x2t(bh, bH + kc * 16 * BNP * 2 + ni * 16);
                ldm_x2t(bl, bL + kc * 16 * BNP * 2 + ni * 16);
                #pragma unroll
                for (int mi = 0; mi < 2; mi++) {
                    mma16816(acc[mi][ni], ah[mi], bh);
                    mma16816(acc[mi][ni], al[mi], bh);
                    mma16816(acc[mi][ni], ah[mi], bl);
                }
            }
        }
        __syncthreads();
    }

    // phase 2: bias + relu, split h1 into smem [f=128][BNP]
    bf16* h1h = dsm;
    bf16* h1l = dsm + 128 * BNP;
    float* srs = (float*)(dsm + 2 * 128 * BNP);
    float* sacc = srs + 64;
    if (tid < 64) srs[tid] = (n0 + tid < N) ? rs[bz * NN + n0 + tid] : 0.f;
    #pragma unroll
    for (int mi = 0; mi < 2; mi++) {
        #pragma unroll
        for (int ni = 0; ni < 4; ni++) {
            int nlb = wn + ni * 8 + 2 * tig;
            #pragma unroll
            for (int h = 0; h < 2; h++) {
                int f = wm + mi * 16 + gid + h * 8;
                #pragma unroll
                for (int e = 0; e < 2; e++) {
                    int nl = nlb + e;
                    float v = fmaxf(acc[mi][ni][h * 2 + e] + bias[f], 0.f);
                    if (n0 + nl >= N) v = 0.f;
                    fsplit(v, &h1h[f * BNP + nl], &h1l[f * BNP + nl]);
                }
            }
        }
    }
    __syncthreads();

    // phase 3: Y2T tile = W2T @ h1T (K=128, A fragments from gmem)
    float acc2[2][4][4] = {};
    uint32_t h1hB = (uint32_t)__cvta_generic_to_shared(h1h);
    uint32_t h1lB = (uint32_t)__cvta_generic_to_shared(h1l);
    #pragma unroll
    for (int kk = 0; kk < 8; kk++) {
        int k0 = kk * 16;
        uint32_t ah2[2][4], al2[2][4];
        #pragma unroll
        for (int mi = 0; mi < 2; mi++) {
            int mrow = wm + mi * 16 + gid;
            const bf16* ph = Wh + mrow * HH + k0 + 2 * tig;
            const bf16* pl = Wl + mrow * HH + k0 + 2 * tig;
            ah2[mi][0] = *(const uint32_t*)ph;
            ah2[mi][1] = *(const uint32_t*)(ph + 8 * HH);
            ah2[mi][2] = *(const uint32_t*)(ph + 8);
            ah2[mi][3] = *(const uint32_t*)(ph + 8 * HH + 8);
            al2[mi][0] = *(const uint32_t*)pl;
            al2[mi][1] = *(const uint32_t*)(pl + 8 * HH);
            al2[mi][2] = *(const uint32_t*)(pl + 8);
            al2[mi][3] = *(const uint32_t*)(pl + 8 * HH + 8);
        }
        uint32_t bbh = h1hB + ((k0 + (lane & 15)) * BNP + wn) * 2;
        uint32_t bbl = h1lB + ((k0 + (lane & 15)) * BNP + wn) * 2;
        #pragma unroll
        for (int ni = 0; ni < 4; ni++) {
            uint32_t bh[2], bl[2];
            ldm_x2t(bh, bbh + ni * 16);
            ldm_x2t(bl, bbl + ni * 16);
            #pragma unroll
            for (int mi = 0; mi < 2; mi++) {
                mma16816(acc2[mi][ni], ah2[mi], bh);
                mma16816(acc2[mi][ni], al2[mi], bh);
                mma16816(acc2[mi][ni], ah2[mi], bl);
            }
        }
    }

    // phase 4: pooled partials
    #pragma unroll
    for (int mi = 0; mi < 2; mi++) {
        #pragma unroll
        for (int h = 0; h < 2; h++) {
            float p = 0.f;
            #pragma unroll
            for (int ni = 0; ni < 4; ni++)
                #pragma unroll
                for (int e = 0; e < 2; e++)
                    p += srs[wn + ni * 8 + 2 * tig + e] * acc2[mi][ni][h * 2 + e];
            p += __shfl_xor_sync(0xffffffffu, p, 1);
            p += __shfl_xor_sync(0xffffffffu, p, 2);
            if (tig == 0) {
                int g = wm + mi * 16 + gid + h * 8;
                sacc[(warp & 1) * 128 + g] = p;
            }
        }
    }
    __syncthreads();
    if (tid < 128)
        partial[((size_t)blockIdx.x * BATCH + bz) * HH + tid] = sacc[tid] + sacc[128 + tid];
}

// ---------------- final head ------------------------------------------------------
__global__ void head2_k(const float* __restrict__ partial, const float* __restrict__ b2,
                        const float* __restrict__ fcw, const float* __restrict__ fcb,
                        float* __restrict__ out) {
    int b = blockIdx.x;
    int f = threadIdx.x;
    __shared__ float sp[HH];
    float s = 0.f;
    #pragma unroll
    for (int t = 0; t < 7; t++) s += partial[((size_t)t * BATCH + b) * HH + f];
    sp[f] = fmaxf(s + b2[f], 0.f);
    __syncthreads();
    if (f < 2) {
        float o = fcb[f];
        for (int q = 0; q < HH; q++) o += sp[q] * fcw[q * 2 + f];
        out[b * 2 + f] = o;
    }
}

// -----------------------------------------------------------------------------------
extern "C" void kernel_launch(void* const* d_in, const int* in_sizes, int n_in,
                              void* d_out, int out_size) {
    const float* x      = (const float*)d_in[0];
    const float* enc1_w = (const float*)d_in[2];
    const float* enc1_b = (const float*)d_in[3];
    const float* enc2_w = (const float*)d_in[4];
    const float* enc2_b = (const float*)d_in[5];
    const float* dec2_w = (const float*)d_in[6];
    const float* dec2_b = (const float*)d_in[7];
    const float* dec1_w = (const float*)d_in[8];
    const float* dec1_b = (const float*)d_in[9];
    const float* gcn1_w = (const float*)d_in[10];
    const float* gcn1_b = (const float*)d_in[11];
    const float* gcn2_w = (const float*)d_in[12];
    const float* gcn2_b = (const float*)d_in[13];
    const float* fc_w   = (const float*)d_in[14];
    const float* fc_b   = (const float*)d_in[15];
    float* out = (float*)d_out;

    float *xf, *delta, *degp, *part, *rs;
    bf16 *ah, *al, *anh, *anl, *o1h, *o1l, *o2ah, *o2al, *o2th, *o2tl;
    bf16 *y1h, *y1l, *wh, *wl;
    ull* thresh;
    cudaGetSymbolAddress((void**)&xf, g_xf);
    cudaGetSymbolAddress((void**)&delta, g_delta);
    cudaGetSymbolAddress((void**)&degp, g_degp);
    cudaGetSymbolAddress((void**)&part, g_part);
    cudaGetSymbolAddress((void**)&ah, g_ah);
    cudaGetSymbolAddress((void**)&al, g_al);
    cudaGetSymbolAddress((void**)&anh, g_anh);
    cudaGetSymbolAddress((void**)&anl, g_anl);
    cudaGetSymbolAddress((void**)&o1h, g_o1h);
    cudaGetSymbolAddress((void**)&o1l, g_o1l);
    cudaGetSymbolAddress((void**)&o2ah, g_o2ah);
    cudaGetSymbolAddress((void**)&o2al, g_o2al);
    cudaGetSymbolAddress((void**)&o2th, g_o2th);
    cudaGetSymbolAddress((void**)&o2tl, g_o2tl);
    cudaGetSymbolAddress((void**)&y1h, g_y1h);
    cudaGetSymbolAddress((void**)&y1l, g_y1l);
    cudaGetSymbolAddress((void**)&wh, g_wh);
    cudaGetSymbolAddress((void**)&wl, g_wl);
    cudaGetSymbolAddress((void**)&thresh, g_thresh);
    cudaGetSymbolAddress((void**)&rs, g_rs);

    cudaFuncSetAttribute((const void*)&bgemm_k<1,1,2,1>, cudaFuncAttributeMaxDynamicSharedMemorySize, SMEM_TOT);
    cudaFuncSetAttribute((const void*)&bgemm_k<1,0,2,1>, cudaFuncAttributeMaxDynamicSharedMemorySize, SMEM_TOT);
    cudaFuncSetAttribute((const void*)&bgemm_k<2,1,2,1>, cudaFuncAttributeMaxDynamicSharedMemorySize, SMEM_TOT);
    cudaFuncSetAttribute((const void*)&bgemm_k<0,0,1,1>, cudaFuncAttributeMaxDynamicSharedMemorySize, SMEM_TOT);
    cudaFuncSetAttribute((const void*)&bgemm_k<0,1,2,1>, cudaFuncAttributeMaxDynamicSharedMemorySize, SMEM_TOT);
    cudaFuncSetAttribute((const void*)&gcn_tail_k, cudaFuncAttributeMaxDynamicSharedMemorySize, SMEM_TOT);
    cudaFuncSetAttribute((const void*)&radix_select_k, cudaFuncAttributeMaxDynamicSharedMemorySize, 49152);

    static cudaStream_t s2 = nullptr;
    static cudaEvent_t evA = nullptr, evB = nullptr, evC = nullptr, evD = nullptr;
    if (!s2) {
        cudaStreamCreateWithFlags(&s2, cudaStreamNonBlocking);
        cudaEventCreateWithFlags(&evA, cudaEventDisableTiming);
        cudaEventCreateWithFlags(&evB, cudaEventDisableTiming);
        cudaEventCreateWithFlags(&evC, cudaEventDisableTiming);
        cudaEventCreateWithFlags(&evD, cudaEventDisableTiming);
    }

    // ---- fork 1: weight splits on s2, fisher on main ----
    cudaEventRecord(evA, 0);
    cudaStreamWaitEvent(s2, evA, 0);
    wsplit_k<<<200, 256, 0, s2>>>(enc1_w, wh + W_E1, wl + W_E1, 51200);
    wsplit_k<<<200, 256, 0, s2>>>(enc2_w, wh + W_E2, wl + W_E2, 51200);
    wsplit_k<<<200, 256, 0, s2>>>(dec2_w, wh + W_D2, wl + W_D2, 51200);
    wsplit_k<<<200, 256, 0, s2>>>(dec1_w, wh + W_D1, wl + W_D1, 51200);
    wsplit_k<<<200, 256, 0, s2>>>(gcn1_w, wh + W_G1, wl + W_G1, 51200);
    wtsplit_k<<<64, 256, 0, s2>>>(gcn2_w, wh + W_G2T, wl + W_G2T);
    cudaEventRecord(evB, s2);

    fisher_k<<<dim3(157, BATCH), 256>>>(x, ah, al);
    cudaStreamWaitEvent(0, evB, 0);

    // 1) out1 = relu(xf @ enc1_w + b) -> split [H][N] per batch, flat M=51200
    bgemm_k<1, 1, 2, 1><<<dim3(2, 400), 256, SMEM_TOT>>>(
        ah, al, 0, NN, wh + W_E1, wl + W_E1, 0, HH, enc1_b,
        nullptr, nullptr, 0, nullptr, o1h, o1l, S_HN, NN, BATCH * NN, HH, NN, NN);

    // 2) out2a = relu(out1 @ enc2_w + b), flat M=16384
    bgemm_k<1, 0, 2, 1><<<dim3(2, 128), 256, SMEM_TOT>>>(
        o1h, o1l, 0, NN, wh + W_E2, wl + W_E2, 0, HH, enc2_b,
        nullptr, nullptr, 0, nullptr, o2ah, o2al, S_HH, HH, BATCH * HH, HH, NN, HH);

    // 3) out2 = relu(out2a @ dec2_w + b + out1[skip pair]) -> out2T split
    bgemm_k<2, 1, 2, 1><<<dim3(7, 128), 256, SMEM_TOT>>>(
        o2ah, o2al, 0, HH, wh + W_D2, wl + W_D2, 0, NN, dec2_b,
        o1h, o1l, NN, nullptr, o2th, o2tl, S_HN, HH, BATCH * HH, NN, HH, HH);

    // 4) delta = out2T @ dec1_w + b, flat M=51200, fp32
    bgemm_k<0, 0, 1, 1><<<dim3(7, 400), 256, SMEM_TOT>>>(
        o2th, o2tl, 0, HH, wh + W_D1, wl + W_D1, 0, NN, dec1_b,
        nullptr, nullptr, 0, delta, nullptr, nullptr, NSQ, NN, BATCH * NN, NN, HH, NN);

    // 5) x2 = xf_split + sym(delta)
    sym2_k<<<dim3(91, BATCH), dim3(8, 32)>>>(xf, delta, ah, al);

    // ---- fork 2: Y1 GEMM on s2, selection chain on main ----
    cudaEventRecord(evC, 0);
    cudaStreamWaitEvent(s2, evC, 0);
    bgemm_k<0, 1, 2, 1><<<dim3(2, 400), 256, SMEM_TOT, s2>>>(
        ah, al, 0, NN, wh + W_G1, wl + W_G1, 0, HH, nullptr,
        nullptr, nullptr, 0, nullptr, y1h, y1l, S_HN, NN, BATCH * NN, HH, NN, NN);
    cudaEventRecord(evD, s2);

    // 6) top-k threshold (1024 threads/CTA)
    radix_select_k<<<BATCH, RNT, 49152>>>(xf, thresh);

    // 7) masked column degree partials
    degp_k<<<dim3(4, BATCH), 512>>>(xf, thresh, degp);

    // 8) warp-per-row An split + row means (dinv in-kernel)
    an_k<<<dim3(50, BATCH), 256>>>(xf, thresh, degp, anh, anl, rs);

    cudaStreamWaitEvent(0, evD, 0);

    // 9) fused GCN tail: h1 -> Y2 -> pooled partials
    gcn_tail_k<<<dim3(7, 1, BATCH), 256, SMEM_TOT>>>(
        y1h, y1l, anh, anl, gcn1_b, wh + W_G2T, wl + W_G2T, rs, part);

    // 10) final head
    head2_k<<<BATCH, 128>>>(part, gcn2_b, fc_w, fc_b, out);
}

// round 17
// speedup vs baseline: 1.0358x; 1.0122x over previous
#include <cuda_runtime.h>
#include <cuda_bf16.h>
#include <cstdint>

#define EPS 1e-9f
#define BATCH 128
#define HB 64                  // half batch
#define NN 400
#define HH 128
#define NSQ (NN * NN)          // 160000
#define NQ4 (NSQ / 4)          // 40000
#define S_HN (HH * NN)         // 51200
#define S_HH (HH * HH)         // 16384
#define KTOP 32000

typedef __nv_bfloat16 bf16;
typedef unsigned long long ull;

// ---------------- scratch -----------------------------------------------------
__device__ float g_xf[BATCH * NSQ];
__device__ float g_delta[BATCH * NSQ];
__device__ float g_degp[BATCH * 4 * NN];
__device__ float g_part[7 * BATCH * HH];
__device__ bf16 g_ah[BATCH * NSQ], g_al[BATCH * NSQ];
__device__ bf16 g_anh[BATCH * NSQ], g_anl[BATCH * NSQ];
__device__ bf16 g_o1h[BATCH * S_HN], g_o1l[BATCH * S_HN];
__device__ bf16 g_o2ah[BATCH * S_HH], g_o2al[BATCH * S_HH];
__device__ bf16 g_o2th[BATCH * S_HN], g_o2tl[BATCH * S_HN];
__device__ bf16 g_y1h[BATCH * S_HN], g_y1l[BATCH * S_HN];
__device__ bf16 g_wh[272384], g_wl[272384];
__device__ ull g_thresh[BATCH];
__device__ float g_rs[BATCH * NN];

#define W_E1 0
#define W_E2 51200
#define W_D2 102400
#define W_D1 153600
#define W_G1 204800
#define W_G2T 256000

__device__ __forceinline__ void fsplit(float v, bf16* h, bf16* l) {
    bf16 hh = __float2bfloat16(v);
    *h = hh;
    *l = __float2bfloat16(v - __bfloat162float(hh));
}
__device__ __forceinline__ void fsplit4(const float* v, uint2* ph, uint2* pl) {
    unsigned short h[4], l[4];
    #pragma unroll
    for (int e = 0; e < 4; e++) {
        bf16 hh = __float2bfloat16(v[e]);
        h[e] = __bfloat16_as_ushort(hh);
        l[e] = __bfloat16_as_ushort(__float2bfloat16(v[e] - __bfloat162float(hh)));
    }
    ph->x = (unsigned)h[0] | ((unsigned)h[1] << 16);
    ph->y = (unsigned)h[2] | ((unsigned)h[3] << 16);
    pl->x = (unsigned)l[0] | ((unsigned)l[1] << 16);
    pl->y = (unsigned)l[2] | ((unsigned)l[3] << 16);
}
__device__ __forceinline__ void unsplit4(uint2 ph, uint2 pl, float* v) {
    v[0] = __uint_as_float(ph.x << 16) + __uint_as_float(pl.x << 16);
    v[1] = __uint_as_float(ph.x & 0xffff0000u) + __uint_as_float(pl.x & 0xffff0000u);
    v[2] = __uint_as_float(ph.y << 16) + __uint_as_float(pl.y << 16);
    v[3] = __uint_as_float(ph.y & 0xffff0000u) + __uint_as_float(pl.y & 0xffff0000u);
}

// ---------------- weight prep --------------------------------------------------
__global__ void wsplit_k(const float* __restrict__ w, bf16* __restrict__ h,
                         bf16* __restrict__ l, int n) {
    int i = blockIdx.x * 256 + threadIdx.x;
    if (i < n) fsplit(w[i], &h[i], &l[i]);
}
__global__ void wtsplit_k(const float* __restrict__ w, bf16* __restrict__ h,
                          bf16* __restrict__ l) {
    int i = blockIdx.x * 256 + threadIdx.x;
    int g = i >> 7, f = i & 127;
    fsplit(w[f * HH + g], &h[i], &l[i]);
}

// ---------------- fisher -> bf16 split (MUFU __logf) ------------------------------
__global__ void fisher_k(const float* __restrict__ x,
                         bf16* __restrict__ xh, bf16* __restrict__ xl) {
    int t = blockIdx.x * 256 + threadIdx.x;
    int b = blockIdx.y;
    if (t >= NQ4) return;
    size_t base = (size_t)b * NSQ;
    float x00 = x[base];
    float d = 0.5f * __logf((1.f + x00 + EPS) / (1.f - x00 + EPS));
    float rd = 1.f / d;
    float4 v = ((const float4*)(x + base))[t];
    float o[4];
    o[0] = 0.5f * __logf((1.f + v.x + EPS) / (1.f - v.x + EPS)) * rd;
    o[1] = 0.5f * __logf((1.f + v.y + EPS) / (1.f - v.y + EPS)) * rd;
    o[2] = 0.5f * __logf((1.f + v.z + EPS) / (1.f - v.z + EPS)) * rd;
    o[3] = 0.5f * __logf((1.f + v.w + EPS) / (1.f - v.w + EPS)) * rd;
    uint2 ph, pl;
    fsplit4(o, &ph, &pl);
    ((uint2*)(xh + base))[t] = ph;
    ((uint2*)(xl + base))[t] = pl;
}

// ---------------- symmetric-pair symmetrize: x2 fp32 + split ---------------------
__global__ void sym2_k(float* __restrict__ x2, const float* __restrict__ delta,
                       bf16* __restrict__ xh, bf16* __restrict__ xl) {
    int b = blockIdx.y;
    int p = blockIdx.x;
    int ti = 0, rem = p;
    while (rem >= 13 - ti) { rem -= 13 - ti; ti++; }
    int tj = ti + rem;
    int i0 = ti * 32, j0 = tj * 32;
    int tx = threadIdx.x, ty = threadIdx.y;
    __shared__ float shA[32][33];
    __shared__ float shB[32][33];
    size_t base = (size_t)b * NSQ;
    bool diag = (ti == tj);

    {
        int r = i0 + ty, c = j0 + tx * 4;
        float4 v = make_float4(0.f, 0.f, 0.f, 0.f);
        if (r < NN && c < NN) v = *(const float4*)&delta[base + (size_t)r * NN + c];
        shA[ty][tx * 4 + 0] = v.x; shA[ty][tx * 4 + 1] = v.y;
        shA[ty][tx * 4 + 2] = v.z; shA[ty][tx * 4 + 3] = v.w;
    }
    if (!diag) {
        int r = j0 + ty, c = i0 + tx * 4;
        float4 v = make_float4(0.f, 0.f, 0.f, 0.f);
        if (r < NN && c < NN) v = *(const float4*)&delta[base + (size_t)r * NN + c];
        shB[ty][tx * 4 + 0] = v.x; shB[ty][tx * 4 + 1] = v.y;
        shB[ty][tx * 4 + 2] = v.z; shB[ty][tx * 4 + 3] = v.w;
    }
    __syncthreads();

    {
        int r = i0 + ty, c0 = j0 + tx * 4;
        if (r < NN && c0 < NN) {
            size_t idx = base + (size_t)r * NN + c0;
            float o[4];
            unsplit4(*(const uint2*)&xh[idx], *(const uint2*)&xl[idx], o);
            #pragma unroll
            for (int e = 0; e < 4; e++) {
                int c = c0 + e;
                float dT = diag ? shA[tx * 4 + e][ty] : shB[tx * 4 + e][ty];
                if (r != c) o[e] += 0.5f * (shA[ty][tx * 4 + e] + dT);
            }
            *(float4*)&x2[idx] = make_float4(o[0], o[1], o[2], o[3]);
            uint2 ph, pl;
            fsplit4(o, &ph, &pl);
            *(uint2*)&xh[idx] = ph;
            *(uint2*)&xl[idx] = pl;
        }
    }
    if (!diag) {
        int r = j0 + ty, c0 = i0 + tx * 4;
        if (r < NN && c0 < NN) {
            size_t idx = base + (size_t)r * NN + c0;
            float o[4];
            unsplit4(*(const uint2*)&xh[idx], *(const uint2*)&xl[idx], o);
            #pragma unroll
            for (int e = 0; e < 4; e++) {
                int c = c0 + e;
                if (r != c) o[e] += 0.5f * (shB[ty][tx * 4 + e] + shA[tx * 4 + e][ty]);
            }
            *(float4*)&x2[idx] = make_float4(o[0], o[1], o[2], o[3]);
            uint2 ph, pl;
            fsplit4(o, &ph, &pl);
            *(uint2*)&xh[idx] = ph;
            *(uint2*)&xl[idx] = pl;
        }
    }
}

// ---------------- keys ------------------------------------------------------------
__device__ __forceinline__ unsigned make_vkey(float v) {
    unsigned u = __float_as_uint(v);
    return (u & 0x80000000u) ? ~u : (u | 0x80000000u);
}
__device__ __forceinline__ ull make_key(float v, unsigned t) {
    return ((ull)make_vkey(v) << 32) | (ull)(~t);
}

// ---------------- exact top-k: two 12-bit passes, 1024 threads --------------------
#define RNT 1024
__global__ void radix_select_k(const float* __restrict__ x2,
                               ull* __restrict__ thresh) {
    const int b = blockIdx.x;
    const float4* xp4 = (const float4*)(x2 + (size_t)b * NSQ);
    extern __shared__ unsigned rsm[];
    unsigned* hist = rsm;                 // [2][4096]
    ull* buf = (ull*)(rsm + 8192);        // [2048]
    __shared__ unsigned wsum[32];
    __shared__ unsigned s_bin, s_rem, s_cnt;
    int tid = threadIdx.x;
    int lane = tid & 31, wid = tid >> 5;
    int hsel = (wid & 1) * 4096;
    if (tid == 0) { s_rem = KTOP; s_cnt = 0; }

    unsigned b1 = 0;
    #pragma unroll
    for (int pass = 0; pass < 2; pass++) {
        for (int i = tid; i < 8192; i += RNT) hist[i] = 0;
        __syncthreads();
        for (int t = tid; t < 40960; t += RNT) {
            bool inr = t < NQ4;
            float4 v = inr ? xp4[t] : make_float4(0.f, 0.f, 0.f, 0.f);
            float vv[4] = {v.x, v.y, v.z, v.w};
            #pragma unroll
            for (int e = 0; e < 4; e++) {
                unsigned vk = make_vkey(vv[e]);
                bool ok = inr && (pass == 0 || (vk >> 20) == b1);
                unsigned bin = (pass == 0) ? (vk >> 20) : ((vk >> 8) & 4095);
                unsigned active = __ballot_sync(0xffffffffu, ok);
                if (ok) {
                    unsigned peers = __match_any_sync(active, bin);
                    int leader = __ffs(peers) - 1;
                    if (lane == leader) atomicAdd(&hist[hsel + bin], __popc(peers));
                }
            }
        }
        __syncthreads();
        unsigned cs = 0;
        #pragma unroll
        for (int k = 0; k < 4; k++) {
            int bin = 4095 - 4 * tid - k;
            cs += hist[bin] + hist[4096 + bin];
        }
        unsigned v = cs;
        #pragma unroll
        for (int o = 1; o < 32; o <<= 1) {
            unsigned u = __shfl_up_sync(0xffffffffu, v, o);
            if (lane >= o) v += u;
        }
        if (lane == 31) wsum[wid] = v;
        __syncthreads();
        if (wid == 0) {
            unsigned w = wsum[lane];
            #pragma unroll
            for (int o = 1; o < 32; o <<= 1) {
                unsigned u = __shfl_up_sync(0xffffffffu, w, o);
                if (lane >= o) w += u;
            }
            wsum[lane] = w;
        }
        __syncthreads();
        unsigned incl = v + (wid ? wsum[wid - 1] : 0);
        unsigned excl = incl - cs;
        unsigned rem = s_rem;
        if (rem > excl && rem <= incl) {
            unsigned c = excl;
            #pragma unroll
            for (int k = 0; k < 4; k++) {
                int bin = 4095 - 4 * tid - k;
                unsigned bc = hist[bin] + hist[4096 + bin];
                if (rem <= c + bc) { s_bin = (unsigned)bin; s_rem = rem - c; break; }
                c += bc;
            }
        }
        __syncthreads();
        if (pass == 0) b1 = s_bin;
    }
    unsigned pref24 = (b1 << 12) | s_bin;
    unsigned remf = s_rem;

    for (int t = tid; t < NQ4; t += RNT) {
        float4 v = xp4[t];
        float vv[4] = {v.x, v.y, v.z, v.w};
        #pragma unroll
        for (int e = 0; e < 4; e++) {
            if ((make_vkey(vv[e]) >> 8) == pref24) {
                unsigned p = atomicAdd(&s_cnt, 1);
                if (p < 2048) buf[p] = make_key(vv[e], (unsigned)(t * 4 + e));
            }
        }
    }
    __syncthreads();
    unsigned n = min(s_cnt, 2048u);
    for (int t = tid; t < (int)n; t += RNT) {
        ull k = buf[t];
        unsigned c = 0;
        for (unsigned j = 0; j < n; j++) c += (buf[j] > k);
        if (c == remf - 1) thresh[b] = k;
    }
}

// ---------------- fused mask + partial column degrees ----------------------------
__global__ void degp_k(const float* __restrict__ x2, const ull* __restrict__ th,
                       float* __restrict__ part) {
    int q = blockIdx.x, b = blockIdx.y;
    int j = threadIdx.x;
    if (j >= NN) return;
    ull thr = th[b];
    const float* xb = x2 + (size_t)b * NSQ;
    float acc = 0.f;
    int i0 = q * 100;
    #pragma unroll 4
    for (int i = i0; i < i0 + 100; i++) {
        float v = xb[(size_t)i * NN + j];
        unsigned r = (unsigned)(i * NN + j);
        float a = (make_key(v, r) >= thr) ? v : 0.f;
        if (i == j && a == 0.f) a = 1.f;
        acc += a;
    }
    part[((size_t)b * 4 + q) * NN + j] = acc;
}

// ------- warp-per-row: dinv (from partials) + mask + An split + row means --------
__global__ void __launch_bounds__(256)
an_k(const float* __restrict__ x2, const ull* __restrict__ th,
     const float* __restrict__ part,
     bf16* __restrict__ anh, bf16* __restrict__ anl,
     float* __restrict__ rs) {
    int b = blockIdx.y;
    int tid = threadIdx.x;
    __shared__ float sdv[NN];
    {
        size_t base = (size_t)b * 4 * NN;
        for (int j = tid; j < NN; j += 256) {
            float s = part[base + j] + part[base + NN + j]
                    + part[base + 2 * NN + j] + part[base + 3 * NN + j];
            float dv = rsqrtf(s);
            if (isinf(dv)) dv = 0.f;
            sdv[j] = dv;
        }
    }
    __syncthreads();
    int warp = tid >> 5, lane = tid & 31;
    int i = blockIdx.x * 8 + warp;
    ull thr = th[b];
    size_t roff = (size_t)b * NSQ + (size_t)i * NN;
    float di = sdv[i];
    float acc = 0.f;
    for (int c = lane; c < 100; c += 32) {
        int j0 = c * 4;
        float4 v = *(const float4*)&x2[roff + j0];
        float vv[4] = {v.x, v.y, v.z, v.w};
        float w[4];
        #pragma unroll
        for (int e = 0; e < 4; e++) {
            unsigned r = (unsigned)(i * NN + j0 + e);
            float a = (make_key(vv[e], r) >= thr) ? vv[e] : 0.f;
            if (i == j0 + e && a == 0.f) a = 1.f;
            w[e] = a * di * sdv[j0 + e];
            acc += w[e];
        }
        uint2 ph, pl;
        fsplit4(w, &ph, &pl);
        *(uint2*)&anh[roff + j0] = ph;
        *(uint2*)&anl[roff + j0] = pl;
    }
    #pragma unroll
    for (int o = 16; o > 0; o >>= 1) acc += __shfl_xor_sync(0xffffffffu, acc, o);
    if (lane == 0) rs[b * NN + i] = acc * (1.f / NN);
}

// =============== 2-stage cp.async bf16 split GEMM ================================
#define BM 128
#define BN 64
#define BK 32
#define BKP 40
#define BNP 72
#define ABUF (BM * BKP * 2)
#define ASTG (2 * ABUF)
#define BBUF (BK * BNP * 2)
#define BSTG (2 * BBUF)
#define SMEM_TOT (2 * (ASTG + BSTG))   // 59392 -> 3 CTAs/SM

__device__ __forceinline__ void ldm_x4(uint32_t* r, uint32_t a) {
    asm volatile("ldmatrix.sync.aligned.m8n8.x4.shared.b16 {%0,%1,%2,%3}, [%4];"
        : "=r"(r[0]), "=r"(r[1]), "=r"(r[2]), "=r"(r[3]) : "r"(a));
}
__device__ __forceinline__ void ldm_x2t(uint32_t* r, uint32_t a) {
    asm volatile("ldmatrix.sync.aligned.m8n8.x2.trans.shared.b16 {%0,%1}, [%2];"
        : "=r"(r[0]), "=r"(r[1]) : "r"(a));
}
__device__ __forceinline__ void mma16816(float* d, const uint32_t* a, const uint32_t* b) {
    asm volatile("mma.sync.aligned.m16n8k16.row.col.f32.bf16.bf16.f32 "
        "{%0,%1,%2,%3}, {%4,%5,%6,%7}, {%8,%9}, {%0,%1,%2,%3};"
        : "+f"(d[0]), "+f"(d[1]), "+f"(d[2]), "+f"(d[3])
        : "r"(a[0]), "r"(a[1]), "r"(a[2]), "r"(a[3]), "r"(b[0]), "r"(b[1]));
}
__device__ __forceinline__ void cpa16(uint32_t dst, const bf16* src, bool p) {
    int sz = p ? 16 : 0;
    asm volatile("cp.async.cg.shared.global [%0], [%1], 16, %2;"
        :: "r"(dst), "l"(src), "r"(sz));
}
__device__ __forceinline__ void cp_commit() {
    asm volatile("cp.async.commit_group;");
}
template<int W> __device__ __forceinline__ void cp_wait() {
    asm volatile("cp.async.wait_group %0;" :: "n"(W));
}

// EPI: 0 none, 1 relu+bias[n], 2 relu+bias[n]+skip(bf16 pair), 3 relu+bias[m]
// OUTF bit0: fp32 C; bit1: split bf16 C. FLAT: batch folded into M.
template<int EPI, int TRANSOUT, int OUTF, int FLAT>
__global__ void __launch_bounds__(256)
bgemm_k(const bf16* __restrict__ Ah, const bf16* __restrict__ Al, size_t sA, int lda,
        const bf16* __restrict__ Bh, const bf16* __restrict__ Bl, size_t sB, int ldb,
        const float* __restrict__ bias,
        const bf16* __restrict__ skH, const bf16* __restrict__ skL, int lds,
        float* __restrict__ Cf, bf16* __restrict__ Ch, bf16* __restrict__ Cl,
        size_t sC, int ldc, int M, int N, int K, int MROWS) {
    int bz = FLAT ? 0 : blockIdx.z;
    if (!FLAT) {
        Ah += (size_t)bz * sA; Al += (size_t)bz * sA;
        Bh += (size_t)bz * sB; Bl += (size_t)bz * sB;
    }

    int n0 = blockIdx.x * BN;
    int m0 = blockIdx.y * BM;

    extern __shared__ bf16 dsm[];
    uint32_t smA = (uint32_t)__cvta_generic_to_shared(dsm);
    uint32_t smB = smA + 2 * ASTG;

    int tid = threadIdx.x;
    int warp = tid >> 5, lane = tid & 31;
    int wm = (warp >> 1) * 32;
    int wn = (warp & 1) * 32;
    int gid = lane >> 2, tig = lane & 3;

    const bf16* aSrc[4]; uint32_t aDst[4]; bool aPm[4]; int aC[4];
    #pragma unroll
    for (int it = 0; it < 4; it++) {
        int idx = tid + it * 256;
        int buf = idx >> 9;
        int rem = idx & 511;
        int r = rem >> 2, c = (rem & 3) * 8;
        int m = m0 + r;
        aPm[it] = m < M;
        aC[it] = c;
        aSrc[it] = (buf ? Al : Ah) + (size_t)(aPm[it] ? m : (M - 1)) * lda + c;
        aDst[it] = smA + buf * ABUF + (r * BKP + c) * 2;
    }
    const bf16* bSrc[2]; uint32_t bDst[2]; bool bPn[2]; int bR[2];
    #pragma unroll
    for (int it = 0; it < 2; it++) {
        int idx = tid + it * 256;
        int buf = idx >> 8;
        int rem = idx & 255;
        int r = rem >> 3, c = (rem & 7) * 8;
        bR[it] = r;
        bPn[it] = (n0 + c) < N;
        bSrc[it] = (buf ? Bl : Bh) + (size_t)r * ldb + (n0 + (bPn[it] ? c : 0));
        bDst[it] = smB + buf * BBUF + (r * BNP + c) * 2;
    }

    auto issue = [&](int k0, int stg) {
        #pragma unroll
        for (int it = 0; it < 4; it++)
            cpa16(aDst[it] + stg * ASTG, aSrc[it] + k0, aPm[it] && (k0 + aC[it] < K));
        #pragma unroll
        for (int it = 0; it < 2; it++)
            cpa16(bDst[it] + stg * BSTG, bSrc[it] + (size_t)k0 * ldb,
                  bPn[it] && (k0 + bR[it] < K));
        cp_commit();
    };

    float acc[2][4][4] = {};

    uint32_t aB0 = smA + ((wm + (lane & 15)) * BKP + (lane >> 4) * 8) * 2;
    uint32_t bB0 = smB + ((lane & 15) * BNP + wn) * 2;

    int nk = (K + BK - 1) / BK;
    issue(0, 0);
    for (int t = 0; t < nk; t++) {
        if (t + 1 < nk) { issue((t + 1) * BK, (t + 1) & 1); cp_wait<1>(); }
        else cp_wait<0>();
        __syncthreads();
        int stg = t & 1;
        uint32_t aH = aB0 + stg * ASTG;
        uint32_t aL = aH + ABUF;
        uint32_t bH = bB0 + stg * BSTG;
        uint32_t bL = bH + BBUF;
        #pragma unroll
        for (int kc = 0; kc < 2; kc++) {
            uint32_t ah[2][4], al[2][4];
            ldm_x4(ah[0], aH + kc * 32);
            ldm_x4(ah[1], aH + 16 * BKP * 2 + kc * 32);
            ldm_x4(al[0], aL + kc * 32);
            ldm_x4(al[1], aL + 16 * BKP * 2 + kc * 32);
            #pragma unroll
            for (int ni = 0; ni < 4; ni++) {
                uint32_t bh[2], bl[2];
                ldm_x2t(bh, bH + kc * 16 * BNP * 2 + ni * 16);
                ldm_x2t(bl, bL + kc * 16 * BNP * 2 + ni * 16);
                #pragma unroll
                for (int mi = 0; mi < 2; mi++) {
                    mma16816(acc[mi][ni], ah[mi], bh);
                    mma16816(acc[mi][ni], al[mi], bh);
                    mma16816(acc[mi][ni], ah[mi], bl);
                }
            }
        }
        __syncthreads();
    }

    #pragma unroll
    for (int mi = 0; mi < 2; mi++) {
        #pragma unroll
        for (int ni = 0; ni < 4; ni++) {
            int cbase = n0 + wn + ni * 8 + 2 * tig;
            #pragma unroll
            for (int h = 0; h < 2; h++) {
                int m = m0 + wm + mi * 16 + gid + h * 8;
                if (m >= M) continue;
                #pragma unroll
                for (int e = 0; e < 2; e++) {
                    int n = cbase + e;
                    if (n >= N) continue;
                    float v = acc[mi][ni][h * 2 + e];
                    if (EPI == 3) v += bias[m];
                    else if (bias) v += bias[n];
                    if (EPI == 2) {
                        size_t so = (size_t)m * lds + n;
                        v += __bfloat162float(skH[so]) + __bfloat162float(skL[so]);
                    }
                    if (EPI >= 1) v = fmaxf(v, 0.f);
                    size_t off;
                    if (FLAT) {
                        if (TRANSOUT) {
                            int bb = m / MROWS;
                            int rr = m - bb * MROWS;
                            off = (size_t)bb * sC + (size_t)n * ldc + rr;
                        } else {
                            off = (size_t)m * ldc + n;
                        }
                    } else {
                        off = (size_t)bz * sC +
                              (TRANSOUT ? ((size_t)n * ldc + m) : ((size_t)m * ldc + n));
                    }
                    if (OUTF & 1) Cf[off] = v;
                    if (OUTF & 2) fsplit(v, &Ch[off], &Cl[off]);
                }
            }
        }
    }
}

// =============== fused GCN tail: h1 GEMM -> Y2 GEMM -> pooled partials ==========
__global__ void __launch_bounds__(256)
gcn_tail_k(const bf16* __restrict__ Ah, const bf16* __restrict__ Al,
           const bf16* __restrict__ Bh, const bf16* __restrict__ Bl,
           const float* __restrict__ bias,
           const bf16* __restrict__ Wh, const bf16* __restrict__ Wl,
           const float* __restrict__ rs, float* __restrict__ partial) {
    const int bz = blockIdx.z;
    Ah += (size_t)bz * S_HN; Al += (size_t)bz * S_HN;
    Bh += (size_t)bz * NSQ;  Bl += (size_t)bz * NSQ;
    const int n0 = blockIdx.x * BN;
    const int N = NN, K = NN;

    extern __shared__ bf16 dsm[];
    uint32_t smA = (uint32_t)__cvta_generic_to_shared(dsm);
    uint32_t smB = smA + 2 * ASTG;

    int tid = threadIdx.x;
    int warp = tid >> 5, lane = tid & 31;
    int wm = (warp >> 1) * 32;
    int wn = (warp & 1) * 32;
    int gid = lane >> 2, tig = lane & 3;

    const bf16* aSrc[4]; uint32_t aDst[4]; int aC[4];
    #pragma unroll
    for (int it = 0; it < 4; it++) {
        int idx = tid + it * 256;
        int buf = idx >> 9;
        int rem = idx & 511;
        int r = rem >> 2, c = (rem & 3) * 8;
        aC[it] = c;
        aSrc[it] = (buf ? Al : Ah) + (size_t)r * NN + c;
        aDst[it] = smA + buf * ABUF + (r * BKP + c) * 2;
    }
    const bf16* bSrc[2]; uint32_t bDst[2]; bool bPn[2]; int bR[2];
    #pragma unroll
    for (int it = 0; it < 2; it++) {
        int idx = tid + it * 256;
        int buf = idx >> 8;
        int rem = idx & 255;
        int r = rem >> 3, c = (rem & 7) * 8;
        bR[it] = r;
        bPn[it] = (n0 + c) < N;
        bSrc[it] = (buf ? Bl : Bh) + (size_t)r * NN + (n0 + (bPn[it] ? c : 0));
        bDst[it] = smB + buf * BBUF + (r * BNP + c) * 2;
    }

    auto issue = [&](int k0, int stg) {
        #pragma unroll
        for (int it = 0; it < 4; it++)
            cpa16(aDst[it] + stg * ASTG, aSrc[it] + k0, (k0 + aC[it] < K));
        #pragma unroll
        for (int it = 0; it < 2; it++)
            cpa16(bDst[it] + stg * BSTG, bSrc[it] + (size_t)k0 * NN,
                  bPn[it] && (k0 + bR[it] < K));
        cp_commit();
    };

    float acc[2][4][4] = {};
    uint32_t aB0 = smA + ((wm + (lane & 15)) * BKP + (lane >> 4) * 8) * 2;
    uint32_t bB0 = smB + ((lane & 15) * BNP + wn) * 2;

    int nk = (K + BK - 1) / BK;   // 13
    issue(0, 0);
    for (int t = 0; t < nk; t++) {
        if (t + 1 < nk) { issue((t + 1) * BK, (t + 1) & 1); cp_wait<1>(); }
        else cp_wait<0>();
        __syncthreads();
        int stg = t & 1;
        uint32_t aH = aB0 + stg * ASTG;
        uint32_t aL = aH + ABUF;
        uint32_t bH = bB0 + stg * BSTG;
        uint32_t bL = bH + BBUF;
        #pragma unroll
        for (int kc = 0; kc < 2; kc++) {
            uint32_t ah[2][4], al[2][4];
            ldm_x4(ah[0], aH + kc * 32);
            ldm_x4(ah[1], aH + 16 * BKP * 2 + kc * 32);
            ldm_x4(al[0], aL + kc * 32);
            ldm_x4(al[1], aL + 16 * BKP * 2 + kc * 32);
            #pragma unroll
            for (int ni = 0; ni < 4; ni++) {
                uint32_t bh[2], bl[2];
                ldm_x2t(bh, bH + kc * 16 * BNP * 2 + ni * 16);
                ldm_x2t(bl, bL + kc * 16 * BNP * 2 + ni * 16);
                #pragma unroll
                for (int mi = 0; mi < 2; mi++) {
                    mma16816(acc[mi][ni], ah[mi], bh);
                    mma16816(acc[mi][ni], al[mi], bh);
                    mma16816(acc[mi][ni], ah[mi], bl);
                }
            }
        }
        __syncthreads();
    }

    // phase 2: bias + relu, split h1 into smem [f=128][BNP]
    bf16* h1h = dsm;
    bf16* h1l = dsm + 128 * BNP;
    float* srs = (float*)(dsm + 2 * 128 * BNP);
    float* sacc = srs + 64;
    if (tid < 64) srs[tid] = (n0 + tid < N) ? rs[bz * NN + n0 + tid] : 0.f;
    #pragma unroll
    for (int mi = 0; mi < 2; mi++) {
        #pragma unroll
        for (int ni = 0; ni < 4; ni++) {
            int nlb = wn + ni * 8 + 2 * tig;
            #pragma unroll
            for (int h = 0; h < 2; h++) {
                int f = wm + mi * 16 + gid + h * 8;
                #pragma unroll
                for (int e = 0; e < 2; e++) {
                    int nl = nlb + e;
                    float v = fmaxf(acc[mi][ni][h * 2 + e] + bias[f], 0.f);
                    if (n0 + nl >= N) v = 0.f;
                    fsplit(v, &h1h[f * BNP + nl], &h1l[f * BNP + nl]);
                }
            }
        }
    }
    __syncthreads();

    // phase 3: Y2T tile = W2T @ h1T (K=128, A fragments from gmem)
    float acc2[2][4][4] = {};
    uint32_t h1hB = (uint32_t)__cvta_generic_to_shared(h1h);
    uint32_t h1lB = (uint32_t)__cvta_generic_to_shared(h1l);
    #pragma unroll
    for (int kk = 0; kk < 8; kk++) {
        int k0 = kk * 16;
        uint32_t ah2[2][4], al2[2][4];
        #pragma unroll
        for (int mi = 0; mi < 2; mi++) {
            int mrow = wm + mi * 16 + gid;
            const bf16* ph = Wh + mrow * HH + k0 + 2 * tig;
            const bf16* pl = Wl + mrow * HH + k0 + 2 * tig;
            ah2[mi][0] = *(const uint32_t*)ph;
            ah2[mi][1] = *(const uint32_t*)(ph + 8 * HH);
            ah2[mi][2] = *(const uint32_t*)(ph + 8);
            ah2[mi][3] = *(const uint32_t*)(ph + 8 * HH + 8);
            al2[mi][0] = *(const uint32_t*)pl;
            al2[mi][1] = *(const uint32_t*)(pl + 8 * HH);
            al2[mi][2] = *(const uint32_t*)(pl + 8);
            al2[mi][3] = *(const uint32_t*)(pl + 8 * HH + 8);
        }
        uint32_t bbh = h1hB + ((k0 + (lane & 15)) * BNP + wn) * 2;
        uint32_t bbl = h1lB + ((k0 + (lane & 15)) * BNP + wn) * 2;
        #pragma unroll
        for (int ni = 0; ni < 4; ni++) {
            uint32_t bh[2], bl[2];
            ldm_x2t(bh, bbh + ni * 16);
            ldm_x2t(bl, bbl + ni * 16);
            #pragma unroll
            for (int mi = 0; mi < 2; mi++) {
                mma16816(acc2[mi][ni], ah2[mi], bh);
                mma16816(acc2[mi][ni], al2[mi], bh);
                mma16816(acc2[mi][ni], ah2[mi], bl);
            }
        }
    }

    // phase 4: pooled partials
    #pragma unroll
    for (int mi = 0; mi < 2; mi++) {
        #pragma unroll
        for (int h = 0; h < 2; h++) {
            float p = 0.f;
            #pragma unroll
            for (int ni = 0; ni < 4; ni++)
                #pragma unroll
                for (int e = 0; e < 2; e++)
                    p += srs[wn + ni * 8 + 2 * tig + e] * acc2[mi][ni][h * 2 + e];
            p += __shfl_xor_sync(0xffffffffu, p, 1);
            p += __shfl_xor_sync(0xffffffffu, p, 2);
            if (tig == 0) {
                int g = wm + mi * 16 + gid + h * 8;
                sacc[(warp & 1) * 128 + g] = p;
            }
        }
    }
    __syncthreads();
    if (tid < 128)
        partial[((size_t)blockIdx.x * BATCH + bz) * HH + tid] = sacc[tid] + sacc[128 + tid];
}

// ---------------- final head ------------------------------------------------------
__global__ void head2_k(const float* __restrict__ partial, const float* __restrict__ b2,
                        const float* __restrict__ fcw, const float* __restrict__ fcb,
                        float* __restrict__ out) {
    int b = blockIdx.x;
    int f = threadIdx.x;
    __shared__ float sp[HH];
    float s = 0.f;
    #pragma unroll
    for (int t = 0; t < 7; t++) s += partial[((size_t)t * BATCH + b) * HH + f];
    sp[f] = fmaxf(s + b2[f], 0.f);
    __syncthreads();
    if (f < 2) {
        float o = fcb[f];
        for (int q = 0; q < HH; q++) o += sp[q] * fcw[q * 2 + f];
        out[b * 2 + f] = o;
    }
}

// -----------------------------------------------------------------------------------
extern "C" void kernel_launch(void* const* d_in, const int* in_sizes, int n_in,
                              void* d_out, int out_size) {
    const float* x      = (const float*)d_in[0];
    const float* enc1_w = (const float*)d_in[2];
    const float* enc1_b = (const float*)d_in[3];
    const float* enc2_w = (const float*)d_in[4];
    const float* enc2_b = (const float*)d_in[5];
    const float* dec2_w = (const float*)d_in[6];
    const float* dec2_b = (const float*)d_in[7];
    const float* dec1_w = (const float*)d_in[8];
    const float* dec1_b = (const float*)d_in[9];
    const float* gcn1_w = (const float*)d_in[10];
    const float* gcn1_b = (const float*)d_in[11];
    const float* gcn2_w = (const float*)d_in[12];
    const float* gcn2_b = (const float*)d_in[13];
    const float* fc_w   = (const float*)d_in[14];
    const float* fc_b   = (const float*)d_in[15];
    float* out = (float*)d_out;

    float *xf, *delta, *degp, *part, *rs;
    bf16 *ah, *al, *anh, *anl, *o1h, *o1l, *o2ah, *o2al, *o2th, *o2tl;
    bf16 *y1h, *y1l, *wh, *wl;
    ull* thresh;
    cudaGetSymbolAddress((void**)&xf, g_xf);
    cudaGetSymbolAddress((void**)&delta, g_delta);
    cudaGetSymbolAddress((void**)&degp, g_degp);
    cudaGetSymbolAddress((void**)&part, g_part);
    cudaGetSymbolAddress((void**)&ah, g_ah);
    cudaGetSymbolAddress((void**)&al, g_al);
    cudaGetSymbolAddress((void**)&anh, g_anh);
    cudaGetSymbolAddress((void**)&anl, g_anl);
    cudaGetSymbolAddress((void**)&o1h, g_o1h);
    cudaGetSymbolAddress((void**)&o1l, g_o1l);
    cudaGetSymbolAddress((void**)&o2ah, g_o2ah);
    cudaGetSymbolAddress((void**)&o2al, g_o2al);
    cudaGetSymbolAddress((void**)&o2th, g_o2th);
    cudaGetSymbolAddress((void**)&o2tl, g_o2tl);
    cudaGetSymbolAddress((void**)&y1h, g_y1h);
    cudaGetSymbolAddress((void**)&y1l, g_y1l);
    cudaGetSymbolAddress((void**)&wh, g_wh);
    cudaGetSymbolAddress((void**)&wl, g_wl);
    cudaGetSymbolAddress((void**)&thresh, g_thresh);
    cudaGetSymbolAddress((void**)&rs, g_rs);

    cudaFuncSetAttribute((const void*)&bgemm_k<1,1,2,1>, cudaFuncAttributeMaxDynamicSharedMemorySize, SMEM_TOT);
    cudaFuncSetAttribute((const void*)&bgemm_k<1,0,2,1>, cudaFuncAttributeMaxDynamicSharedMemorySize, SMEM_TOT);
    cudaFuncSetAttribute((const void*)&bgemm_k<2,1,2,1>, cudaFuncAttributeMaxDynamicSharedMemorySize, SMEM_TOT);
    cudaFuncSetAttribute((const void*)&bgemm_k<0,0,1,1>, cudaFuncAttributeMaxDynamicSharedMemorySize, SMEM_TOT);
    cudaFuncSetAttribute((const void*)&bgemm_k<0,1,2,1>, cudaFuncAttributeMaxDynamicSharedMemorySize, SMEM_TOT);
    cudaFuncSetAttribute((const void*)&gcn_tail_k, cudaFuncAttributeMaxDynamicSharedMemorySize, SMEM_TOT);
    cudaFuncSetAttribute((const void*)&radix_select_k, cudaFuncAttributeMaxDynamicSharedMemorySize, 49152);

    static cudaStream_t s2 = nullptr;
    static cudaEvent_t evA = nullptr, evW = nullptr, ev2 = nullptr;
    if (!s2) {
        cudaStreamCreateWithFlags(&s2, cudaStreamNonBlocking);
        cudaEventCreateWithFlags(&evA, cudaEventDisableTiming);
        cudaEventCreateWithFlags(&evW, cudaEventDisableTiming);
        cudaEventCreateWithFlags(&ev2, cudaEventDisableTiming);
    }

    // ---- fork: weights on s2 first, then chain2 (batches 64..127) on s2;
    //      chain1 (batches 0..63) on main. Kernels are per-batch independent. ----
    cudaEventRecord(evA, 0);
    cudaStreamWaitEvent(s2, evA, 0);
    wsplit_k<<<200, 256, 0, s2>>>(enc1_w, wh + W_E1, wl + W_E1, 51200);
    wsplit_k<<<200, 256, 0, s2>>>(enc2_w, wh + W_E2, wl + W_E2, 51200);
    wsplit_k<<<200, 256, 0, s2>>>(dec2_w, wh + W_D2, wl + W_D2, 51200);
    wsplit_k<<<200, 256, 0, s2>>>(dec1_w, wh + W_D1, wl + W_D1, 51200);
    wsplit_k<<<200, 256, 0, s2>>>(gcn1_w, wh + W_G1, wl + W_G1, 51200);
    wtsplit_k<<<64, 256, 0, s2>>>(gcn2_w, wh + W_G2T, wl + W_G2T);
    cudaEventRecord(evW, s2);

    for (int h = 0; h < 2; h++) {
        cudaStream_t st = (h == 0) ? (cudaStream_t)0 : s2;
        size_t xoff  = (size_t)h * HB * NSQ;      // x, xf, ah/al, anh/anl, delta
        size_t o1off = (size_t)h * HB * S_HN;     // o1, o2t, y1
        size_t o2off = (size_t)h * HB * S_HH;     // o2a
        size_t dgoff = (size_t)h * HB * 4 * NN;   // degp
        size_t rsoff = (size_t)h * HB * NN;       // rs
        size_t ptoff = (size_t)h * HB * HH;       // partial (inner-batch offset)
        int    thoff = h * HB;                    // thresh
        int    MB    = HB * NN;                   // flat M for N=400-row operands
        int    MH    = HB * HH;                   // flat M for H=128-row operands

        fisher_k<<<dim3(157, HB), 256, 0, st>>>(x + xoff, ah + xoff, al + xoff);
        if (h == 0) cudaStreamWaitEvent(0, evW, 0);   // chain1 needs weights

        // G1: out1 = relu(xf @ enc1_w + b) -> split [H][N] per batch
        bgemm_k<1, 1, 2, 1><<<dim3(2, 200), 256, SMEM_TOT, st>>>(
            ah + xoff, al + xoff, 0, NN, wh + W_E1, wl + W_E1, 0, HH, enc1_b,
            nullptr, nullptr, 0, nullptr, o1h + o1off, o1l + o1off,
            S_HN, NN, MB, HH, NN, NN);

        // G2: out2a = relu(out1 @ enc2_w + b)
        bgemm_k<1, 0, 2, 1><<<dim3(2, 64), 256, SMEM_TOT, st>>>(
            o1h + o1off, o1l + o1off, 0, NN, wh + W_E2, wl + W_E2, 0, HH, enc2_b,
            nullptr, nullptr, 0, nullptr, o2ah + o2off, o2al + o2off,
            S_HH, HH, MH, HH, NN, HH);

        // G3: out2 = relu(out2a @ dec2_w + b + out1) -> out2T split
        bgemm_k<2, 1, 2, 1><<<dim3(7, 64), 256, SMEM_TOT, st>>>(
            o2ah + o2off, o2al + o2off, 0, HH, wh + W_D2, wl + W_D2, 0, NN, dec2_b,
            o1h + o1off, o1l + o1off, NN, nullptr, o2th + o1off, o2tl + o1off,
            S_HN, HH, MH, NN, HH, HH);

        // G4: delta = out2T @ dec1_w + b, fp32
        bgemm_k<0, 0, 1, 1><<<dim3(7, 200), 256, SMEM_TOT, st>>>(
            o2th + o1off, o2tl + o1off, 0, HH, wh + W_D1, wl + W_D1, 0, NN, dec1_b,
            nullptr, nullptr, 0, delta + xoff, nullptr, nullptr,
            NSQ, NN, MB, NN, HH, NN);

        // sym
        sym2_k<<<dim3(91, HB), dim3(8, 32), 0, st>>>(
            xf + xoff, delta + xoff, ah + xoff, al + xoff);

        // Y1 = x2 @ gcn1_w -> Y1T split
        bgemm_k<0, 1, 2, 1><<<dim3(2, 200), 256, SMEM_TOT, st>>>(
            ah + xoff, al + xoff, 0, NN, wh + W_G1, wl + W_G1, 0, HH, nullptr,
            nullptr, nullptr, 0, nullptr, y1h + o1off, y1l + o1off,
            S_HN, NN, MB, HH, NN, NN);

        // selection chain
        radix_select_k<<<HB, RNT, 49152, st>>>(xf + xoff, thresh + thoff);
        degp_k<<<dim3(4, HB), 512, 0, st>>>(xf + xoff, thresh + thoff, degp + dgoff);
        an_k<<<dim3(50, HB), 256, 0, st>>>(
            xf + xoff, thresh + thoff, degp + dgoff,
            anh + xoff, anl + xoff, rs + rsoff);

        // fused GCN tail
        gcn_tail_k<<<dim3(7, 1, HB), 256, SMEM_TOT, st>>>(
            y1h + o1off, y1l + o1off, anh + xoff, anl + xoff, gcn1_b,
            wh + W_G2T, wl + W_G2T, rs + rsoff, part + ptoff);
    }

    cudaEventRecord(ev2, s2);
    cudaStreamWaitEvent(0, ev2, 0);

    head2_k<<<BATCH, 128>>>(part, gcn2_b, fc_w, fc_b, out);
}